// round 1
// baseline (speedup 1.0000x reference)
#include <cuda_runtime.h>
#include <cstdint>

typedef unsigned long long ull;

#define NMAX 100032
#define HID 64

// ---------------- packed fp32x2 helpers (Blackwell) ----------------
__device__ __forceinline__ ull fma2(ull a, ull b, ull c) {
    ull d;
    asm("fma.rn.f32x2 %0, %1, %2, %3;" : "=l"(d) : "l"(a), "l"(b), "l"(c));
    return d;
}
__device__ __forceinline__ ull pack2(float x, float y) {
    ull r; asm("mov.b64 %0, {%1, %2};" : "=l"(r) : "f"(x), "f"(y)); return r;
}
__device__ __forceinline__ float2 unpack2(ull v) {
    float2 r; asm("mov.b64 {%0, %1}, %2;" : "=f"(r.x), "=f"(r.y) : "l"(v)); return r;
}

__device__ __forceinline__ float gelu_tanh(float x) {
    float x3 = x * x * x;
    return 0.5f * x * (1.0f + tanhf(0.79788456080286535588f * (x + 0.044715f * x3)));
}

// ---------------- scratch (device globals; no runtime alloc) ----------------
__device__ float g_h0 [NMAX * HID];
__device__ float g_h1 [NMAX * HID];
__device__ float g_q  [NMAX * HID];
__device__ float g_kT [NMAX * HID];
__device__ float g_mT [NMAX * HID];
__device__ float g_agg[NMAX * HID];
__device__ float g_den[NMAX * 4];

// =====================================================================
// Kernel 1: projection  h = x @ Wp + bp   (n x 768) @ (768 x 64)
// Tiled GEMM: BM=128, BN=64, BK=16, 256 threads, f32x2 packed FMA.
// =====================================================================
__global__ __launch_bounds__(256) void proj_kernel(
    const float* __restrict__ x, const float* __restrict__ Wp,
    const float* __restrict__ bp, float* __restrict__ h, int n)
{
    __shared__ float sA[16][132];   // [k][m], padded
    __shared__ float sB[16][64];    // [k][n]

    const int tx = threadIdx.x;
    const int cx = tx & 15;         // col group: cols cx*4 .. cx*4+3
    const int rx = tx >> 4;         // row group: rows rx*8 .. rx*8+7
    const int r_base = rx * 8;
    const int c_base = cx * 4;
    const int gm = blockIdx.x * 128;

    ull acc01[8], acc23[8];
#pragma unroll
    for (int r = 0; r < 8; r++) { acc01[r] = 0ull; acc23[r] = 0ull; }

    for (int k0 = 0; k0 < 768; k0 += 16) {
        // load A tile (x), transposed into [k][m]
#pragma unroll
        for (int it = 0; it < 2; it++) {
            int f4  = tx + it * 256;
            int row = f4 >> 2;
            int kq  = (f4 & 3) * 4;
            float4 v = make_float4(0.f, 0.f, 0.f, 0.f);
            int grow = gm + row;
            if (grow < n)
                v = *(const float4*)&x[(size_t)grow * 768 + k0 + kq];
            sA[kq + 0][row] = v.x;
            sA[kq + 1][row] = v.y;
            sA[kq + 2][row] = v.z;
            sA[kq + 3][row] = v.w;
        }
        // load B tile (Wp)
        {
            int row = tx >> 4;
            int c4  = (tx & 15) * 4;
            float4 v = *(const float4*)&Wp[(size_t)(k0 + row) * 64 + c4];
            *(float4*)&sB[row][c4] = v;
        }
        __syncthreads();

#pragma unroll
        for (int kk = 0; kk < 16; kk++) {
            float4 a0 = *(const float4*)&sA[kk][r_base];
            float4 a1 = *(const float4*)&sA[kk][r_base + 4];
            float4 b  = *(const float4*)&sB[kk][c_base];
            ull b01 = pack2(b.x, b.y);
            ull b23 = pack2(b.z, b.w);
            float ar[8] = {a0.x, a0.y, a0.z, a0.w, a1.x, a1.y, a1.z, a1.w};
#pragma unroll
            for (int r = 0; r < 8; r++) {
                ull a2 = pack2(ar[r], ar[r]);
                acc01[r] = fma2(a2, b01, acc01[r]);
                acc23[r] = fma2(a2, b23, acc23[r]);
            }
        }
        __syncthreads();
    }

    float4 bb = *(const float4*)&bp[c_base];
#pragma unroll
    for (int r = 0; r < 8; r++) {
        int row = gm + r_base + r;
        if (row < n) {
            float2 p01 = unpack2(acc01[r]);
            float2 p23 = unpack2(acc23[r]);
            float4 o = make_float4(p01.x + bb.x, p01.y + bb.y,
                                   p23.x + bb.z, p23.y + bb.w);
            *(float4*)&h[(size_t)row * 64 + c_base] = o;
        }
    }
}

// =====================================================================
// Kernel 2: per-node QKV + relation transforms + zero agg/den.
// Warp handles 4 nodes; lane owns output cols (2*lane, 2*lane+1).
//   q  = h@Wq + bq
//   kT[h,f] = sum_d (h@Wk+bk)[h,d] * a_rel[h,d,f]
//   mT[h,f] = sum_d (h@Wv+bv)[h,d] * m_rel[h,d,f]
// =====================================================================
__global__ __launch_bounds__(256) void qkv_kernel(
    const float* __restrict__ h,
    const float* __restrict__ Wk, const float* __restrict__ bk,
    const float* __restrict__ Wq, const float* __restrict__ bq,
    const float* __restrict__ Wv, const float* __restrict__ bv,
    const float* __restrict__ Ar, const float* __restrict__ Mr,
    float* __restrict__ qo, float* __restrict__ kTo, float* __restrict__ mTo,
    float* __restrict__ agg, float* __restrict__ den, int n)
{
    __shared__ float kbuf[8][4][64];
    __shared__ float vbuf[8][4][64];

    const int w     = threadIdx.x >> 5;
    const int lane  = threadIdx.x & 31;
    const int node0 = (blockIdx.x * 8 + w) * 4;
    if (node0 >= n) return;
    const int c0 = lane * 2;

    float2 hv[4];
#pragma unroll
    for (int i = 0; i < 4; i++) {
        int nd = node0 + i;
        hv[i] = (nd < n) ? *(const float2*)&h[(size_t)nd * 64 + c0]
                         : make_float2(0.f, 0.f);
    }

    ull ka[4] = {0,0,0,0}, qa[4] = {0,0,0,0}, va[4] = {0,0,0,0};
#pragma unroll 8
    for (int j = 0; j < 64; j += 2) {
        ull wk0 = *(const ull*)&Wk[(j    ) * 64 + c0];
        ull wq0 = *(const ull*)&Wq[(j    ) * 64 + c0];
        ull wv0 = *(const ull*)&Wv[(j    ) * 64 + c0];
        ull wk1 = *(const ull*)&Wk[(j + 1) * 64 + c0];
        ull wq1 = *(const ull*)&Wq[(j + 1) * 64 + c0];
        ull wv1 = *(const ull*)&Wv[(j + 1) * 64 + c0];
#pragma unroll
        for (int i = 0; i < 4; i++) {
            float h0 = __shfl_sync(0xffffffffu, hv[i].x, j >> 1);
            float h1 = __shfl_sync(0xffffffffu, hv[i].y, j >> 1);
            ull a0 = pack2(h0, h0);
            ull a1 = pack2(h1, h1);
            ka[i] = fma2(a0, wk0, ka[i]); ka[i] = fma2(a1, wk1, ka[i]);
            qa[i] = fma2(a0, wq0, qa[i]); qa[i] = fma2(a1, wq1, qa[i]);
            va[i] = fma2(a0, wv0, va[i]); va[i] = fma2(a1, wv1, va[i]);
        }
    }

    const float bk0 = bk[c0], bk1 = bk[c0 + 1];
    const float bq0 = bq[c0], bq1 = bq[c0 + 1];
    const float bv0 = bv[c0], bv1 = bv[c0 + 1];
#pragma unroll
    for (int i = 0; i < 4; i++) {
        float2 kk = unpack2(ka[i]); kk.x += bk0; kk.y += bk1;
        float2 qq = unpack2(qa[i]); qq.x += bq0; qq.y += bq1;
        float2 vv = unpack2(va[i]); vv.x += bv0; vv.y += bv1;
        int nd = node0 + i;
        if (nd < n) *(float2*)&qo[(size_t)nd * 64 + c0] = qq;
        kbuf[w][i][c0] = kk.x; kbuf[w][i][c0 + 1] = kk.y;
        vbuf[w][i][c0] = vv.x; vbuf[w][i][c0 + 1] = vv.y;
    }
    __syncwarp();

    // relation transforms: lane's cols (c0,c0+1) belong to head hd, f=c0&15
    const int hd = lane >> 3;
    const int f0 = c0 & 15;
    const float* Arh = Ar + hd * 256;
    const float* Mrh = Mr + hd * 256;
    ull kt[4] = {0,0,0,0}, mt[4] = {0,0,0,0};
#pragma unroll
    for (int d = 0; d < 16; d++) {
        ull ar = *(const ull*)&Arh[d * 16 + f0];
        ull mr = *(const ull*)&Mrh[d * 16 + f0];
#pragma unroll
        for (int i = 0; i < 4; i++) {
            float ks = kbuf[w][i][(hd << 4) + d];
            float vs = vbuf[w][i][(hd << 4) + d];
            kt[i] = fma2(pack2(ks, ks), ar, kt[i]);
            mt[i] = fma2(pack2(vs, vs), mr, mt[i]);
        }
    }

#pragma unroll
    for (int i = 0; i < 4; i++) {
        int nd = node0 + i;
        if (nd < n) {
            *(float2*)&kTo[(size_t)nd * 64 + c0] = unpack2(kt[i]);
            *(float2*)&mTo[(size_t)nd * 64 + c0] = unpack2(mt[i]);
            *(float2*)&agg[(size_t)nd * 64 + c0] = make_float2(0.f, 0.f);
            if ((lane & 7) == 0) den[(size_t)nd * 4 + hd] = 0.f;
        }
    }
}

// =====================================================================
// Kernel 3: edge pass. Half-warp per edge (16 lanes, 4 floats/lane).
//   w = exp( dot(kT[src], q[dst]) * p_rel[h] / sqrt(D) )   per head
//   agg[dst] += w * mT[src]   (red.v4),  den[dst,h] += w
// (softmax max-shift dropped — logits are tiny; normalization deferred)
// =====================================================================
__global__ __launch_bounds__(256) void edge_kernel(
    const int* __restrict__ ei,
    const float* __restrict__ q, const float* __restrict__ kT,
    const float* __restrict__ mT, const float* __restrict__ prel,
    float* __restrict__ agg, float* __restrict__ den, int ne)
{
    const int warp = blockIdx.x * 8 + (threadIdx.x >> 5);
    const int lane = threadIdx.x & 31;
    const int sub  = lane >> 4;
    const int sl   = lane & 15;
    const int col  = sl * 4;
    const int hd   = sl >> 2;

    int e = warp * 2 + sub;
    bool ok = (e < ne);
    int ec = ok ? e : 0;

    const int s = ei[ec];
    const int d = ei[ne + ec];

    float4 kt = *(const float4*)&kT[(size_t)s * 64 + col];
    float4 qd = *(const float4*)&q [(size_t)d * 64 + col];
    float p = kt.x * qd.x + kt.y * qd.y + kt.z * qd.z + kt.w * qd.w;
    p += __shfl_xor_sync(0xffffffffu, p, 1);
    p += __shfl_xor_sync(0xffffffffu, p, 2);
    float wgt = __expf(p * prel[hd] * 0.25f);   // 1/sqrt(16)

    float4 mt = *(const float4*)&mT[(size_t)s * 64 + col];
    if (ok) {
        float* ap = &agg[(size_t)d * 64 + col];
        asm volatile("red.global.add.v4.f32 [%0], {%1,%2,%3,%4};"
                     :: "l"(ap), "f"(mt.x * wgt), "f"(mt.y * wgt),
                        "f"(mt.z * wgt), "f"(mt.w * wgt) : "memory");
        if ((sl & 3) == 0) {
            asm volatile("red.global.add.f32 [%0], %1;"
                         :: "l"(&den[(size_t)d * 4 + hd]), "f"(wgt) : "memory");
        }
    }
}

// =====================================================================
// Kernel 4: node epilogue.
//   g = gelu(agg / (den + 1e-16));  out = g@Wo + bo
//   h' = relu( sig(skip)*out + (1-sig(skip))*h )
// =====================================================================
__global__ __launch_bounds__(256) void out_kernel(
    const float* __restrict__ hin,
    const float* __restrict__ agg, const float* __restrict__ den,
    const float* __restrict__ Wo, const float* __restrict__ bo,
    const float* __restrict__ skp, float* __restrict__ hout, int n)
{
    const int w     = threadIdx.x >> 5;
    const int lane  = threadIdx.x & 31;
    const int node0 = (blockIdx.x * 8 + w) * 4;
    if (node0 >= n) return;
    const int c0 = lane * 2;
    const int hd = lane >> 3;

    float2 g[4];
#pragma unroll
    for (int i = 0; i < 4; i++) {
        int nd = node0 + i;
        if (nd < n) {
            float2 a = *(const float2*)&agg[(size_t)nd * 64 + c0];
            float dn = den[(size_t)nd * 4 + hd] + 1e-16f;
            float inv = 1.0f / dn;
            g[i].x = gelu_tanh(a.x * inv);
            g[i].y = gelu_tanh(a.y * inv);
        } else {
            g[i] = make_float2(0.f, 0.f);
        }
    }

    ull acc[4] = {0,0,0,0};
#pragma unroll 8
    for (int j = 0; j < 64; j += 2) {
        ull w0 = *(const ull*)&Wo[(j    ) * 64 + c0];
        ull w1 = *(const ull*)&Wo[(j + 1) * 64 + c0];
#pragma unroll
        for (int i = 0; i < 4; i++) {
            float g0 = __shfl_sync(0xffffffffu, g[i].x, j >> 1);
            float g1 = __shfl_sync(0xffffffffu, g[i].y, j >> 1);
            acc[i] = fma2(pack2(g0, g0), w0, acc[i]);
            acc[i] = fma2(pack2(g1, g1), w1, acc[i]);
        }
    }

    const float sg = 1.0f / (1.0f + __expf(-skp[0]));
    const float b0 = bo[c0], b1 = bo[c0 + 1];
#pragma unroll
    for (int i = 0; i < 4; i++) {
        int nd = node0 + i;
        if (nd < n) {
            float2 o = unpack2(acc[i]);
            o.x += b0; o.y += b1;
            float2 hp = *(const float2*)&hin[(size_t)nd * 64 + c0];
            float r0 = sg * o.x + (1.0f - sg) * hp.x;
            float r1 = sg * o.y + (1.0f - sg) * hp.y;
            r0 = fmaxf(r0, 0.f);
            r1 = fmaxf(r1, 0.f);
            *(float2*)&hout[(size_t)nd * 64 + c0] = make_float2(r0, r1);
        }
    }
}

// =====================================================================
// Kernel 5: classifier.  out = relu(h@Wc1+bc1) @ Wc2 + bc2
// Warp handles 4 nodes; lane owns hc col = lane (32 cols).
// =====================================================================
__global__ __launch_bounds__(256) void cls_kernel(
    const float* __restrict__ h,
    const float* __restrict__ Wc1, const float* __restrict__ bc1,
    const float* __restrict__ Wc2, const float* __restrict__ bc2,
    float* __restrict__ out, int n)
{
    const int w     = threadIdx.x >> 5;
    const int lane  = threadIdx.x & 31;
    const int node0 = (blockIdx.x * 8 + w) * 4;
    if (node0 >= n) return;
    const int c0 = lane * 2;

    float2 hv[4];
#pragma unroll
    for (int i = 0; i < 4; i++) {
        int nd = node0 + i;
        hv[i] = (nd < n) ? *(const float2*)&h[(size_t)nd * 64 + c0]
                         : make_float2(0.f, 0.f);
    }

    float acc[4] = {0.f, 0.f, 0.f, 0.f};
#pragma unroll 8
    for (int j = 0; j < 64; j += 2) {
        float w0 = Wc1[(j    ) * 32 + lane];
        float w1 = Wc1[(j + 1) * 32 + lane];
#pragma unroll
        for (int i = 0; i < 4; i++) {
            float h0 = __shfl_sync(0xffffffffu, hv[i].x, j >> 1);
            float h1 = __shfl_sync(0xffffffffu, hv[i].y, j >> 1);
            acc[i] = fmaf(h0, w0, acc[i]);
            acc[i] = fmaf(h1, w1, acc[i]);
        }
    }

    const float b1 = bc1[lane];
    float2 w2 = *(const float2*)&Wc2[lane * 2];
    const float bo0 = bc2[0], bo1 = bc2[1];
#pragma unroll
    for (int i = 0; i < 4; i++) {
        float hc = fmaxf(acc[i] + b1, 0.f);
        float o0 = hc * w2.x;
        float o1 = hc * w2.y;
#pragma unroll
        for (int m = 16; m >= 1; m >>= 1) {
            o0 += __shfl_xor_sync(0xffffffffu, o0, m);
            o1 += __shfl_xor_sync(0xffffffffu, o1, m);
        }
        int nd = node0 + i;
        if (lane == 0 && nd < n) {
            *(float2*)&out[(size_t)nd * 2] = make_float2(o0 + bo0, o1 + bo1);
        }
    }
}

// =====================================================================
extern "C" void kernel_launch(void* const* d_in, const int* in_sizes, int n_in,
                              void* d_out, int out_size)
{
    const float* x     = (const float*)d_in[0];
    const int*   ei    = (const int*)  d_in[1];
    const float* Wp    = (const float*)d_in[2];
    const float* bp    = (const float*)d_in[3];
    const float* Wk    = (const float*)d_in[4];
    const float* bk    = (const float*)d_in[5];
    const float* Wq    = (const float*)d_in[6];
    const float* bq    = (const float*)d_in[7];
    const float* Wv    = (const float*)d_in[8];
    const float* bv    = (const float*)d_in[9];
    const float* a_rel = (const float*)d_in[10];
    const float* m_rel = (const float*)d_in[11];
    const float* p_rel = (const float*)d_in[12];
    const float* Wo    = (const float*)d_in[13];
    const float* bo    = (const float*)d_in[14];
    const float* skp   = (const float*)d_in[15];
    const float* Wc1   = (const float*)d_in[16];
    const float* bc1   = (const float*)d_in[17];
    const float* Wc2   = (const float*)d_in[18];
    const float* bc2   = (const float*)d_in[19];

    const int n  = in_sizes[0] / 768;
    const int ne = in_sizes[1] / 2;

    float *h0, *h1, *qb, *ktb, *mtb, *aggb, *denb;
    cudaGetSymbolAddress((void**)&h0,   g_h0);
    cudaGetSymbolAddress((void**)&h1,   g_h1);
    cudaGetSymbolAddress((void**)&qb,   g_q);
    cudaGetSymbolAddress((void**)&ktb,  g_kT);
    cudaGetSymbolAddress((void**)&mtb,  g_mT);
    cudaGetSymbolAddress((void**)&aggb, g_agg);
    cudaGetSymbolAddress((void**)&denb, g_den);

    const int gProj = (n + 127) / 128;
    const int gNode = (n + 31) / 32;
    const int gEdge = (ne + 15) / 16;

    proj_kernel<<<gProj, 256>>>(x, Wp, bp, h0, n);

    const float* hin = h0;
    float* hout = h1;
    for (int l = 0; l < 2; l++) {
        qkv_kernel<<<gNode, 256>>>(hin,
                                   Wk + l * 4096, bk + l * 64,
                                   Wq + l * 4096, bq + l * 64,
                                   Wv + l * 4096, bv + l * 64,
                                   a_rel + l * 1024, m_rel + l * 1024,
                                   qb, ktb, mtb, aggb, denb, n);
        edge_kernel<<<gEdge, 256>>>(ei, qb, ktb, mtb, p_rel + l * 4,
                                    aggb, denb, ne);
        out_kernel<<<gNode, 256>>>(hin, aggb, denb,
                                   Wo + l * 4096, bo + l * 64,
                                   skp + l, hout, n);
        const float* t = hin; hin = hout; hout = (float*)t;
    }

    cls_kernel<<<gNode, 256>>>(hin, Wc1, bc1, Wc2, bc2, (float*)d_out, n);
}

// round 2
// speedup vs baseline: 1.1199x; 1.1199x over previous
#include <cuda_runtime.h>
#include <cuda_bf16.h>
#include <cstdint>

typedef unsigned long long ull;

#define NMAX 100032
#define EMAX 1664000
#define HID 64

// ---------------- packed fp32x2 helpers (Blackwell) ----------------
__device__ __forceinline__ ull fma2(ull a, ull b, ull c) {
    ull d;
    asm("fma.rn.f32x2 %0, %1, %2, %3;" : "=l"(d) : "l"(a), "l"(b), "l"(c));
    return d;
}
__device__ __forceinline__ ull pack2(float x, float y) {
    ull r; asm("mov.b64 %0, {%1, %2};" : "=l"(r) : "f"(x), "f"(y)); return r;
}
__device__ __forceinline__ float2 unpack2(ull v) {
    float2 r; asm("mov.b64 {%0, %1}, %2;" : "=f"(r.x), "=f"(r.y) : "l"(v)); return r;
}

__device__ __forceinline__ float gelu_tanh(float x) {
    float x3 = x * x * x;
    return 0.5f * x * (1.0f + tanhf(0.79788456080286535588f * (x + 0.044715f * x3)));
}

// ---------------- scratch (device globals; no runtime alloc) ----------------
__device__ float g_h0 [NMAX * HID];
__device__ float g_h1 [NMAX * HID];
__device__ float g_q  [NMAX * HID];
__device__ __nv_bfloat16 g_km[NMAX * 128];   // per node: [0:64) kT, [64:128) mT
__device__ int   g_cnt [NMAX];
__device__ int   g_cnt2[NMAX];
__device__ int   g_off [NMAX];
__device__ int   g_part[128];
__device__ int   g_partScan[128];
__device__ int   g_part2[128];
__device__ int   g_csr [EMAX];

// =====================================================================
// CSR construction
// =====================================================================
__global__ void zero_kernel(int* a, int* b, int n) {
    int i = blockIdx.x * blockDim.x + threadIdx.x;
    if (i < n) { a[i] = 0; b[i] = 0; }
}

__global__ void hist_kernel(const int* __restrict__ ei, int* __restrict__ cnt, int ne) {
    int e = blockIdx.x * blockDim.x + threadIdx.x;
    if (e < ne) atomicAdd(&cnt[ei[ne + e]], 1);
}

// exclusive scan over blocks of 1024; writes per-block total to part[]
__global__ __launch_bounds__(1024) void scan1_kernel(
    const int* __restrict__ in, int* __restrict__ out, int* __restrict__ part, int n)
{
    __shared__ int wsum[32];
    int t = threadIdx.x;
    int i = blockIdx.x * 1024 + t;
    int v = (i < n) ? in[i] : 0;
    int x = v;
#pragma unroll
    for (int d = 1; d < 32; d <<= 1) {
        int y = __shfl_up_sync(0xffffffffu, x, d);
        if ((t & 31) >= d) x += y;
    }
    if ((t & 31) == 31) wsum[t >> 5] = x;
    __syncthreads();
    if (t < 32) {
        int s = wsum[t];
        int sx = s;
#pragma unroll
        for (int d = 1; d < 32; d <<= 1) {
            int y = __shfl_up_sync(0xffffffffu, sx, d);
            if (t >= d) sx += y;
        }
        wsum[t] = sx - s;   // exclusive prefix of warp sums
    }
    __syncthreads();
    int excl = x - v + wsum[t >> 5];
    if (i < n) out[i] = excl;
    if (t == 1023 && part) part[blockIdx.x] = x + wsum[31];
}

__global__ void scan3_kernel(int* __restrict__ off, const int* __restrict__ partScan, int n) {
    int i = blockIdx.x * 1024 + threadIdx.x;
    if (i < n) off[i] += partScan[blockIdx.x];
}

__global__ void scatter_kernel(const int* __restrict__ ei,
                               const int* __restrict__ off, int* __restrict__ cnt2,
                               int* __restrict__ csr, int ne)
{
    int e = blockIdx.x * blockDim.x + threadIdx.x;
    if (e < ne) {
        int s = ei[e];
        int d = ei[ne + e];
        int pos = off[d] + atomicAdd(&cnt2[d], 1);
        csr[pos] = s;
    }
}

// =====================================================================
// Kernel 1: projection  h = x @ Wp + bp   (n x 768) @ (768 x 64)
// =====================================================================
__global__ __launch_bounds__(256) void proj_kernel(
    const float* __restrict__ x, const float* __restrict__ Wp,
    const float* __restrict__ bp, float* __restrict__ h, int n)
{
    __shared__ float sA[16][132];
    __shared__ float sB[16][64];

    const int tx = threadIdx.x;
    const int cx = tx & 15;
    const int rx = tx >> 4;
    const int r_base = rx * 8;
    const int c_base = cx * 4;
    const int gm = blockIdx.x * 128;

    ull acc01[8], acc23[8];
#pragma unroll
    for (int r = 0; r < 8; r++) { acc01[r] = 0ull; acc23[r] = 0ull; }

    for (int k0 = 0; k0 < 768; k0 += 16) {
#pragma unroll
        for (int it = 0; it < 2; it++) {
            int f4  = tx + it * 256;
            int row = f4 >> 2;
            int kq  = (f4 & 3) * 4;
            float4 v = make_float4(0.f, 0.f, 0.f, 0.f);
            int grow = gm + row;
            if (grow < n)
                v = *(const float4*)&x[(size_t)grow * 768 + k0 + kq];
            sA[kq + 0][row] = v.x;
            sA[kq + 1][row] = v.y;
            sA[kq + 2][row] = v.z;
            sA[kq + 3][row] = v.w;
        }
        {
            int row = tx >> 4;
            int c4  = (tx & 15) * 4;
            float4 v = *(const float4*)&Wp[(size_t)(k0 + row) * 64 + c4];
            *(float4*)&sB[row][c4] = v;
        }
        __syncthreads();

#pragma unroll
        for (int kk = 0; kk < 16; kk++) {
            float4 a0 = *(const float4*)&sA[kk][r_base];
            float4 a1 = *(const float4*)&sA[kk][r_base + 4];
            float4 b  = *(const float4*)&sB[kk][c_base];
            ull b01 = pack2(b.x, b.y);
            ull b23 = pack2(b.z, b.w);
            float ar[8] = {a0.x, a0.y, a0.z, a0.w, a1.x, a1.y, a1.z, a1.w};
#pragma unroll
            for (int r = 0; r < 8; r++) {
                ull a2 = pack2(ar[r], ar[r]);
                acc01[r] = fma2(a2, b01, acc01[r]);
                acc23[r] = fma2(a2, b23, acc23[r]);
            }
        }
        __syncthreads();
    }

    float4 bb = *(const float4*)&bp[c_base];
#pragma unroll
    for (int r = 0; r < 8; r++) {
        int row = gm + r_base + r;
        if (row < n) {
            float2 p01 = unpack2(acc01[r]);
            float2 p23 = unpack2(acc23[r]);
            float4 o = make_float4(p01.x + bb.x, p01.y + bb.y,
                                   p23.x + bb.z, p23.y + bb.w);
            *(float4*)&h[(size_t)row * 64 + c_base] = o;
        }
    }
}

// =====================================================================
// Kernel 2: per-node QKV + relation transforms.
//   q (fp32) -> g_q ;  kT,mT (bf16, interleaved) -> g_km
// =====================================================================
__global__ __launch_bounds__(256) void qkv_kernel(
    const float* __restrict__ h,
    const float* __restrict__ Wk, const float* __restrict__ bk,
    const float* __restrict__ Wq, const float* __restrict__ bq,
    const float* __restrict__ Wv, const float* __restrict__ bv,
    const float* __restrict__ Ar, const float* __restrict__ Mr,
    float* __restrict__ qo, __nv_bfloat16* __restrict__ kmo, int n)
{
    __shared__ float kbuf[8][4][64];
    __shared__ float vbuf[8][4][64];

    const int w     = threadIdx.x >> 5;
    const int lane  = threadIdx.x & 31;
    const int node0 = (blockIdx.x * 8 + w) * 4;
    if (node0 >= n) return;
    const int c0 = lane * 2;

    float2 hv[4];
#pragma unroll
    for (int i = 0; i < 4; i++) {
        int nd = node0 + i;
        hv[i] = (nd < n) ? *(const float2*)&h[(size_t)nd * 64 + c0]
                         : make_float2(0.f, 0.f);
    }

    ull ka[4] = {0,0,0,0}, qa[4] = {0,0,0,0}, va[4] = {0,0,0,0};
#pragma unroll 8
    for (int j = 0; j < 64; j += 2) {
        ull wk0 = *(const ull*)&Wk[(j    ) * 64 + c0];
        ull wq0 = *(const ull*)&Wq[(j    ) * 64 + c0];
        ull wv0 = *(const ull*)&Wv[(j    ) * 64 + c0];
        ull wk1 = *(const ull*)&Wk[(j + 1) * 64 + c0];
        ull wq1 = *(const ull*)&Wq[(j + 1) * 64 + c0];
        ull wv1 = *(const ull*)&Wv[(j + 1) * 64 + c0];
#pragma unroll
        for (int i = 0; i < 4; i++) {
            float h0 = __shfl_sync(0xffffffffu, hv[i].x, j >> 1);
            float h1 = __shfl_sync(0xffffffffu, hv[i].y, j >> 1);
            ull a0 = pack2(h0, h0);
            ull a1 = pack2(h1, h1);
            ka[i] = fma2(a0, wk0, ka[i]); ka[i] = fma2(a1, wk1, ka[i]);
            qa[i] = fma2(a0, wq0, qa[i]); qa[i] = fma2(a1, wq1, qa[i]);
            va[i] = fma2(a0, wv0, va[i]); va[i] = fma2(a1, wv1, va[i]);
        }
    }

    const float bk0 = bk[c0], bk1 = bk[c0 + 1];
    const float bq0 = bq[c0], bq1 = bq[c0 + 1];
    const float bv0 = bv[c0], bv1 = bv[c0 + 1];
#pragma unroll
    for (int i = 0; i < 4; i++) {
        float2 kk = unpack2(ka[i]); kk.x += bk0; kk.y += bk1;
        float2 qq = unpack2(qa[i]); qq.x += bq0; qq.y += bq1;
        float2 vv = unpack2(va[i]); vv.x += bv0; vv.y += bv1;
        int nd = node0 + i;
        if (nd < n) *(float2*)&qo[(size_t)nd * 64 + c0] = qq;
        kbuf[w][i][c0] = kk.x; kbuf[w][i][c0 + 1] = kk.y;
        vbuf[w][i][c0] = vv.x; vbuf[w][i][c0 + 1] = vv.y;
    }
    __syncwarp();

    const int hd = lane >> 3;
    const int f0 = c0 & 15;
    const float* Arh = Ar + hd * 256;
    const float* Mrh = Mr + hd * 256;
    ull kt[4] = {0,0,0,0}, mt[4] = {0,0,0,0};
#pragma unroll
    for (int d = 0; d < 16; d++) {
        ull ar = *(const ull*)&Arh[d * 16 + f0];
        ull mr = *(const ull*)&Mrh[d * 16 + f0];
#pragma unroll
        for (int i = 0; i < 4; i++) {
            float ks = kbuf[w][i][(hd << 4) + d];
            float vs = vbuf[w][i][(hd << 4) + d];
            kt[i] = fma2(pack2(ks, ks), ar, kt[i]);
            mt[i] = fma2(pack2(vs, vs), mr, mt[i]);
        }
    }

#pragma unroll
    for (int i = 0; i < 4; i++) {
        int nd = node0 + i;
        if (nd < n) {
            float2 k2 = unpack2(kt[i]);
            float2 m2 = unpack2(mt[i]);
            __nv_bfloat16* row = kmo + (size_t)nd * 128;
            *(__nv_bfloat162*)(row + c0)      = __float22bfloat162_rn(k2);
            *(__nv_bfloat162*)(row + 64 + c0) = __float22bfloat162_rn(m2);
        }
    }
}

// =====================================================================
// Kernel 3: fused edge aggregation + epilogue. One warp per dst node.
//   per edge: w = exp( dot(kT[src], q[dst]) * p_rel / 4 )
//   acc += w * mT[src]; wsum += w
//   g = gelu(acc / (wsum + 1e-16)); out = g@Wo + bo
//   h' = relu( sig(skip)*out + (1-sig(skip))*h )
// =====================================================================
__global__ __launch_bounds__(256) void layer_kernel(
    const float* __restrict__ hin, const float* __restrict__ q,
    const __nv_bfloat16* __restrict__ km,
    const int* __restrict__ off, const int* __restrict__ cnt,
    const int* __restrict__ csr,
    const float* __restrict__ prel,
    const float* __restrict__ Wo, const float* __restrict__ bo,
    const float* __restrict__ skp,
    float* __restrict__ hout, int n)
{
    __shared__ float sWo[64 * 64];

    // cooperative Wo load (all threads, before any exit)
    {
        int t4 = threadIdx.x * 4;
#pragma unroll
        for (int i = 0; i < 4; i++) {
            int idx = t4 + i * 1024;
            *(float4*)&sWo[idx] = *(const float4*)&Wo[idx];
        }
    }
    __syncthreads();

    const int w    = threadIdx.x >> 5;
    const int lane = threadIdx.x & 31;
    const int node = blockIdx.x * 8 + w;
    if (node >= n) return;

    const int c0 = lane * 2;
    const int hd = lane >> 3;
    const float pr = prel[hd] * 0.25f;   // 1/sqrt(16)

    const float2 qv = *(const float2*)&q[(size_t)node * 64 + c0];
    const int base = off[node];
    const int deg  = cnt[node];

    float acc0 = 0.f, acc1 = 0.f, wsum = 0.f;

    for (int i0 = 0; i0 < deg; i0 += 32) {
        int m = deg - i0; if (m > 32) m = 32;
        int sreg = (i0 + lane < deg) ? csr[base + i0 + lane] : 0;
#pragma unroll 4
        for (int j = 0; j < m; j++) {
            int s = __shfl_sync(0xffffffffu, sreg, j);
            const __nv_bfloat16* row = km + (size_t)s * 128;
            float2 kt = __bfloat1622float2(*(const __nv_bfloat162*)(row + c0));
            float2 mt = __bfloat1622float2(*(const __nv_bfloat162*)(row + 64 + c0));
            float p = kt.x * qv.x + kt.y * qv.y;
            p += __shfl_xor_sync(0xffffffffu, p, 1);
            p += __shfl_xor_sync(0xffffffffu, p, 2);
            p += __shfl_xor_sync(0xffffffffu, p, 4);
            float wgt = __expf(p * pr);
            acc0 = fmaf(wgt, mt.x, acc0);
            acc1 = fmaf(wgt, mt.y, acc1);
            wsum += wgt;
        }
    }

    const float inv = 1.0f / (wsum + 1e-16f);
    float2 g;
    g.x = gelu_tanh(acc0 * inv);
    g.y = gelu_tanh(acc1 * inv);

    // out = g @ Wo  (warp GEMV via shuffle)
    ull acc = 0ull;
#pragma unroll 8
    for (int j = 0; j < 64; j += 2) {
        ull w0 = *(const ull*)&sWo[(j    ) * 64 + c0];
        ull w1 = *(const ull*)&sWo[(j + 1) * 64 + c0];
        float g0 = __shfl_sync(0xffffffffu, g.x, j >> 1);
        float g1 = __shfl_sync(0xffffffffu, g.y, j >> 1);
        acc = fma2(pack2(g0, g0), w0, acc);
        acc = fma2(pack2(g1, g1), w1, acc);
    }

    const float sg = 1.0f / (1.0f + __expf(-skp[0]));
    float2 o = unpack2(acc);
    o.x += bo[c0];
    o.y += bo[c0 + 1];
    float2 hp = *(const float2*)&hin[(size_t)node * 64 + c0];
    float r0 = fmaxf(sg * o.x + (1.0f - sg) * hp.x, 0.f);
    float r1 = fmaxf(sg * o.y + (1.0f - sg) * hp.y, 0.f);
    *(float2*)&hout[(size_t)node * 64 + c0] = make_float2(r0, r1);
}

// =====================================================================
// Kernel 4: classifier.  out = relu(h@Wc1+bc1) @ Wc2 + bc2
// =====================================================================
__global__ __launch_bounds__(256) void cls_kernel(
    const float* __restrict__ h,
    const float* __restrict__ Wc1, const float* __restrict__ bc1,
    const float* __restrict__ Wc2, const float* __restrict__ bc2,
    float* __restrict__ out, int n)
{
    const int w     = threadIdx.x >> 5;
    const int lane  = threadIdx.x & 31;
    const int node0 = (blockIdx.x * 8 + w) * 4;
    if (node0 >= n) return;
    const int c0 = lane * 2;

    float2 hv[4];
#pragma unroll
    for (int i = 0; i < 4; i++) {
        int nd = node0 + i;
        hv[i] = (nd < n) ? *(const float2*)&h[(size_t)nd * 64 + c0]
                         : make_float2(0.f, 0.f);
    }

    float acc[4] = {0.f, 0.f, 0.f, 0.f};
#pragma unroll 8
    for (int j = 0; j < 64; j += 2) {
        float w0 = Wc1[(j    ) * 32 + lane];
        float w1 = Wc1[(j + 1) * 32 + lane];
#pragma unroll
        for (int i = 0; i < 4; i++) {
            float h0 = __shfl_sync(0xffffffffu, hv[i].x, j >> 1);
            float h1 = __shfl_sync(0xffffffffu, hv[i].y, j >> 1);
            acc[i] = fmaf(h0, w0, acc[i]);
            acc[i] = fmaf(h1, w1, acc[i]);
        }
    }

    const float b1 = bc1[lane];
    float2 w2 = *(const float2*)&Wc2[lane * 2];
    const float bo0 = bc2[0], bo1 = bc2[1];
#pragma unroll
    for (int i = 0; i < 4; i++) {
        float hc = fmaxf(acc[i] + b1, 0.f);
        float o0 = hc * w2.x;
        float o1 = hc * w2.y;
#pragma unroll
        for (int m = 16; m >= 1; m >>= 1) {
            o0 += __shfl_xor_sync(0xffffffffu, o0, m);
            o1 += __shfl_xor_sync(0xffffffffu, o1, m);
        }
        int nd = node0 + i;
        if (lane == 0 && nd < n) {
            *(float2*)&out[(size_t)nd * 2] = make_float2(o0 + bo0, o1 + bo1);
        }
    }
}

// =====================================================================
extern "C" void kernel_launch(void* const* d_in, const int* in_sizes, int n_in,
                              void* d_out, int out_size)
{
    const float* x     = (const float*)d_in[0];
    const int*   ei    = (const int*)  d_in[1];
    const float* Wp    = (const float*)d_in[2];
    const float* bp    = (const float*)d_in[3];
    const float* Wk    = (const float*)d_in[4];
    const float* bk    = (const float*)d_in[5];
    const float* Wq    = (const float*)d_in[6];
    const float* bq    = (const float*)d_in[7];
    const float* Wv    = (const float*)d_in[8];
    const float* bv    = (const float*)d_in[9];
    const float* a_rel = (const float*)d_in[10];
    const float* m_rel = (const float*)d_in[11];
    const float* p_rel = (const float*)d_in[12];
    const float* Wo    = (const float*)d_in[13];
    const float* bo    = (const float*)d_in[14];
    const float* skp   = (const float*)d_in[15];
    const float* Wc1   = (const float*)d_in[16];
    const float* bc1   = (const float*)d_in[17];
    const float* Wc2   = (const float*)d_in[18];
    const float* bc2   = (const float*)d_in[19];

    const int n  = in_sizes[0] / 768;
    const int ne = in_sizes[1] / 2;

    float *h0, *h1, *qb;
    __nv_bfloat16 *kmb;
    int *cnt, *cnt2, *off, *part, *partScan, *part2, *csr;
    cudaGetSymbolAddress((void**)&h0,  g_h0);
    cudaGetSymbolAddress((void**)&h1,  g_h1);
    cudaGetSymbolAddress((void**)&qb,  g_q);
    cudaGetSymbolAddress((void**)&kmb, g_km);
    cudaGetSymbolAddress((void**)&cnt, g_cnt);
    cudaGetSymbolAddress((void**)&cnt2, g_cnt2);
    cudaGetSymbolAddress((void**)&off, g_off);
    cudaGetSymbolAddress((void**)&part, g_part);
    cudaGetSymbolAddress((void**)&partScan, g_partScan);
    cudaGetSymbolAddress((void**)&part2, g_part2);
    cudaGetSymbolAddress((void**)&csr, g_csr);

    const int gProj = (n + 127) / 128;
    const int gNode = (n + 31) / 32;    // 4 nodes/warp kernels
    const int gWarp = (n + 7) / 8;      // 1 node/warp kernels
    const int gE    = (ne + 255) / 256;
    const int nScanBlocks = (n + 1023) / 1024;

    // ---- CSR build (once; valid for both layers) ----
    zero_kernel<<<(n + 255) / 256, 256>>>(cnt, cnt2, n);
    hist_kernel<<<gE, 256>>>(ei, cnt, ne);
    scan1_kernel<<<nScanBlocks, 1024>>>(cnt, off, part, n);
    scan1_kernel<<<1, 1024>>>(part, partScan, part2, nScanBlocks);
    scan3_kernel<<<nScanBlocks, 1024>>>(off, partScan, n);
    scatter_kernel<<<gE, 256>>>(ei, off, cnt2, csr, ne);

    // ---- input projection ----
    proj_kernel<<<gProj, 256>>>(x, Wp, bp, h0, n);

    // ---- HGT layers ----
    const float* hin = h0;
    float* hout = h1;
    for (int l = 0; l < 2; l++) {
        qkv_kernel<<<gNode, 256>>>(hin,
                                   Wk + l * 4096, bk + l * 64,
                                   Wq + l * 4096, bq + l * 64,
                                   Wv + l * 4096, bv + l * 64,
                                   a_rel + l * 1024, m_rel + l * 1024,
                                   qb, kmb, n);
        layer_kernel<<<gWarp, 256>>>(hin, qb, kmb, off, cnt, csr,
                                     p_rel + l * 4,
                                     Wo + l * 4096, bo + l * 64, skp + l,
                                     hout, n);
        const float* t = hin; hin = hout; hout = (float*)t;
    }

    cls_kernel<<<gNode, 256>>>(hin, Wc1, bc1, Wc2, bc2, (float*)d_out, n);
}

// round 3
// speedup vs baseline: 1.2142x; 1.0842x over previous
#include <cuda_runtime.h>
#include <cuda_bf16.h>
#include <cstdint>

typedef unsigned long long ull;

#define NMAX 100032
#define EMAX 1664000
#define HID 64

// ---------------- packed fp32x2 helpers (Blackwell) ----------------
__device__ __forceinline__ ull fma2(ull a, ull b, ull c) {
    ull d;
    asm("fma.rn.f32x2 %0, %1, %2, %3;" : "=l"(d) : "l"(a), "l"(b), "l"(c));
    return d;
}
__device__ __forceinline__ ull pack2(float x, float y) {
    ull r; asm("mov.b64 %0, {%1, %2};" : "=l"(r) : "f"(x), "f"(y)); return r;
}
__device__ __forceinline__ float2 unpack2(ull v) {
    float2 r; asm("mov.b64 {%0, %1}, %2;" : "=f"(r.x), "=f"(r.y) : "l"(v)); return r;
}

__device__ __forceinline__ void cp16(void* smem, const void* gmem) {
    unsigned saddr = (unsigned)__cvta_generic_to_shared(smem);
    asm volatile("cp.async.cg.shared.global [%0], [%1], 16;" :: "r"(saddr), "l"(gmem));
}
__device__ __forceinline__ void cp_commit() {
    asm volatile("cp.async.commit_group;");
}
template <int N>
__device__ __forceinline__ void cp_wait() {
    asm volatile("cp.async.wait_group %0;" :: "n"(N));
}

__device__ __forceinline__ float gelu_tanh(float x) {
    float x3 = x * x * x;
    return 0.5f * x * (1.0f + tanhf(0.79788456080286535588f * (x + 0.044715f * x3)));
}

// ---------------- scratch (device globals; no runtime alloc) ----------------
__device__ float g_h0 [NMAX * HID];
__device__ float g_h1 [NMAX * HID];
__device__ float g_q  [NMAX * HID];
__device__ __nv_bfloat16 g_km[NMAX * 128];   // per node: [0:64) kT, [64:128) mT
__device__ int   g_cnt [NMAX];
__device__ int   g_cnt2[NMAX];
__device__ int   g_off [NMAX];
__device__ int   g_part[128];
__device__ int   g_partScan[128];
__device__ int   g_part2[128];
__device__ int   g_csr [EMAX];

// =====================================================================
// CSR construction
// =====================================================================
__global__ void zero_kernel(int* a, int* b, int n) {
    int i = blockIdx.x * blockDim.x + threadIdx.x;
    if (i < n) { a[i] = 0; b[i] = 0; }
}

__global__ void hist_kernel(const int* __restrict__ ei, int* __restrict__ cnt, int ne) {
    int e = blockIdx.x * blockDim.x + threadIdx.x;
    if (e < ne) atomicAdd(&cnt[ei[ne + e]], 1);
}

__global__ __launch_bounds__(1024) void scan1_kernel(
    const int* __restrict__ in, int* __restrict__ out, int* __restrict__ part, int n)
{
    __shared__ int wsum[32];
    int t = threadIdx.x;
    int i = blockIdx.x * 1024 + t;
    int v = (i < n) ? in[i] : 0;
    int x = v;
#pragma unroll
    for (int d = 1; d < 32; d <<= 1) {
        int y = __shfl_up_sync(0xffffffffu, x, d);
        if ((t & 31) >= d) x += y;
    }
    if ((t & 31) == 31) wsum[t >> 5] = x;
    __syncthreads();
    if (t < 32) {
        int s = wsum[t];
        int sx = s;
#pragma unroll
        for (int d = 1; d < 32; d <<= 1) {
            int y = __shfl_up_sync(0xffffffffu, sx, d);
            if (t >= d) sx += y;
        }
        wsum[t] = sx - s;
    }
    __syncthreads();
    int excl = x - v + wsum[t >> 5];
    if (i < n) out[i] = excl;
    if (t == 1023 && part) part[blockIdx.x] = x + wsum[31];
}

__global__ void scan3_kernel(int* __restrict__ off, const int* __restrict__ partScan, int n) {
    int i = blockIdx.x * 1024 + threadIdx.x;
    if (i < n) off[i] += partScan[blockIdx.x];
}

__global__ void scatter_kernel(const int* __restrict__ ei,
                               const int* __restrict__ off, int* __restrict__ cnt2,
                               int* __restrict__ csr, int ne)
{
    int e = blockIdx.x * blockDim.x + threadIdx.x;
    if (e < ne) {
        int s = ei[e];
        int d = ei[ne + e];
        int pos = off[d] + atomicAdd(&cnt2[d], 1);
        csr[pos] = s;
    }
}

// =====================================================================
// Kernel 1: projection  h = x @ Wp + bp   (n x 768) @ (768 x 64)
// cp.async double-buffered, BM=128, BN=64, BK=16.
// Thread owns 8 rows x 4 cols. sA natural layout [row][k] (pad 20).
// =====================================================================
__global__ __launch_bounds__(256) void proj_kernel(
    const float* __restrict__ x, const float* __restrict__ Wp,
    const float* __restrict__ bp, float* __restrict__ h, int n)
{
    __shared__ float sA[2][128][20];   // pad 20 keeps 16B alignment for cp.async
    __shared__ float sB[2][16][64];

    const int tx = threadIdx.x;
    const int cx = tx & 15;
    const int rx = tx >> 4;
    const int r_base = rx * 8;
    const int c_base = cx * 4;
    const int gm = blockIdx.x * 128;

    // prefetch lambda-ish macro
    auto prefetch = [&](int t) {
        int k0 = t * 16;
        int buf = t & 1;
#pragma unroll
        for (int it = 0; it < 2; it++) {
            int chunk = tx + it * 256;          // 0..511
            int row = chunk >> 2;
            int kq  = (chunk & 3) * 4;
            int grow = gm + row;
            float* dst = &sA[buf][row][kq];
            if (grow < n)
                cp16(dst, &x[(size_t)grow * 768 + k0 + kq]);
            else
                *(float4*)dst = make_float4(0.f, 0.f, 0.f, 0.f);
        }
        {
            int row = tx >> 4;
            int c4  = (tx & 15) * 4;
            cp16(&sB[buf][row][c4], &Wp[(size_t)(k0 + row) * 64 + c4]);
        }
    };

    ull acc01[8], acc23[8];
#pragma unroll
    for (int r = 0; r < 8; r++) { acc01[r] = 0ull; acc23[r] = 0ull; }

    prefetch(0);
    cp_commit();

    for (int t = 0; t < 48; t++) {
        if (t + 1 < 48) {
            prefetch(t + 1);
            cp_commit();
            cp_wait<1>();
        } else {
            cp_wait<0>();
        }
        __syncthreads();

        const int buf = t & 1;
#pragma unroll
        for (int kk = 0; kk < 16; kk += 2) {
            float2 a2[8];
#pragma unroll
            for (int r = 0; r < 8; r++)
                a2[r] = *(const float2*)&sA[buf][r_base + r][kk];
            float4 b0 = *(const float4*)&sB[buf][kk    ][c_base];
            float4 b1 = *(const float4*)&sB[buf][kk + 1][c_base];
            ull b0_01 = pack2(b0.x, b0.y), b0_23 = pack2(b0.z, b0.w);
            ull b1_01 = pack2(b1.x, b1.y), b1_23 = pack2(b1.z, b1.w);
#pragma unroll
            for (int r = 0; r < 8; r++) {
                ull ax = pack2(a2[r].x, a2[r].x);
                ull ay = pack2(a2[r].y, a2[r].y);
                acc01[r] = fma2(ax, b0_01, acc01[r]);
                acc23[r] = fma2(ax, b0_23, acc23[r]);
                acc01[r] = fma2(ay, b1_01, acc01[r]);
                acc23[r] = fma2(ay, b1_23, acc23[r]);
            }
        }
        __syncthreads();
    }

    float4 bb = *(const float4*)&bp[c_base];
#pragma unroll
    for (int r = 0; r < 8; r++) {
        int row = gm + r_base + r;
        if (row < n) {
            float2 p01 = unpack2(acc01[r]);
            float2 p23 = unpack2(acc23[r]);
            float4 o = make_float4(p01.x + bb.x, p01.y + bb.y,
                                   p23.x + bb.z, p23.y + bb.w);
            *(float4*)&h[(size_t)row * 64 + c_base] = o;
        }
    }
}

// =====================================================================
// Kernel 2: per-node QKV + relation transforms.
//   q (fp32) -> g_q ;  kT,mT (bf16, interleaved) -> g_km
// =====================================================================
__global__ __launch_bounds__(256) void qkv_kernel(
    const float* __restrict__ h,
    const float* __restrict__ Wk, const float* __restrict__ bk,
    const float* __restrict__ Wq, const float* __restrict__ bq,
    const float* __restrict__ Wv, const float* __restrict__ bv,
    const float* __restrict__ Ar, const float* __restrict__ Mr,
    float* __restrict__ qo, __nv_bfloat16* __restrict__ kmo, int n)
{
    __shared__ float kbuf[8][4][64];
    __shared__ float vbuf[8][4][64];

    const int w     = threadIdx.x >> 5;
    const int lane  = threadIdx.x & 31;
    const int node0 = (blockIdx.x * 8 + w) * 4;
    if (node0 >= n) return;
    const int c0 = lane * 2;

    float2 hv[4];
#pragma unroll
    for (int i = 0; i < 4; i++) {
        int nd = node0 + i;
        hv[i] = (nd < n) ? *(const float2*)&h[(size_t)nd * 64 + c0]
                         : make_float2(0.f, 0.f);
    }

    ull ka[4] = {0,0,0,0}, qa[4] = {0,0,0,0}, va[4] = {0,0,0,0};
#pragma unroll 8
    for (int j = 0; j < 64; j += 2) {
        ull wk0 = *(const ull*)&Wk[(j    ) * 64 + c0];
        ull wq0 = *(const ull*)&Wq[(j    ) * 64 + c0];
        ull wv0 = *(const ull*)&Wv[(j    ) * 64 + c0];
        ull wk1 = *(const ull*)&Wk[(j + 1) * 64 + c0];
        ull wq1 = *(const ull*)&Wq[(j + 1) * 64 + c0];
        ull wv1 = *(const ull*)&Wv[(j + 1) * 64 + c0];
#pragma unroll
        for (int i = 0; i < 4; i++) {
            float h0 = __shfl_sync(0xffffffffu, hv[i].x, j >> 1);
            float h1 = __shfl_sync(0xffffffffu, hv[i].y, j >> 1);
            ull a0 = pack2(h0, h0);
            ull a1 = pack2(h1, h1);
            ka[i] = fma2(a0, wk0, ka[i]); ka[i] = fma2(a1, wk1, ka[i]);
            qa[i] = fma2(a0, wq0, qa[i]); qa[i] = fma2(a1, wq1, qa[i]);
            va[i] = fma2(a0, wv0, va[i]); va[i] = fma2(a1, wv1, va[i]);
        }
    }

    const float bk0 = bk[c0], bk1 = bk[c0 + 1];
    const float bq0 = bq[c0], bq1 = bq[c0 + 1];
    const float bv0 = bv[c0], bv1 = bv[c0 + 1];
#pragma unroll
    for (int i = 0; i < 4; i++) {
        float2 kk = unpack2(ka[i]); kk.x += bk0; kk.y += bk1;
        float2 qq = unpack2(qa[i]); qq.x += bq0; qq.y += bq1;
        float2 vv = unpack2(va[i]); vv.x += bv0; vv.y += bv1;
        int nd = node0 + i;
        if (nd < n) *(float2*)&qo[(size_t)nd * 64 + c0] = qq;
        kbuf[w][i][c0] = kk.x; kbuf[w][i][c0 + 1] = kk.y;
        vbuf[w][i][c0] = vv.x; vbuf[w][i][c0 + 1] = vv.y;
    }
    __syncwarp();

    const int hd = lane >> 3;
    const int f0 = c0 & 15;
    const float* Arh = Ar + hd * 256;
    const float* Mrh = Mr + hd * 256;
    ull kt[4] = {0,0,0,0}, mt[4] = {0,0,0,0};
#pragma unroll
    for (int d = 0; d < 16; d++) {
        ull ar = *(const ull*)&Arh[d * 16 + f0];
        ull mr = *(const ull*)&Mrh[d * 16 + f0];
#pragma unroll
        for (int i = 0; i < 4; i++) {
            float ks = kbuf[w][i][(hd << 4) + d];
            float vs = vbuf[w][i][(hd << 4) + d];
            kt[i] = fma2(pack2(ks, ks), ar, kt[i]);
            mt[i] = fma2(pack2(vs, vs), mr, mt[i]);
        }
    }

#pragma unroll
    for (int i = 0; i < 4; i++) {
        int nd = node0 + i;
        if (nd < n) {
            float2 k2 = unpack2(kt[i]);
            float2 m2 = unpack2(mt[i]);
            __nv_bfloat16* row = kmo + (size_t)nd * 128;
            *(__nv_bfloat162*)(row + c0)      = __float22bfloat162_rn(k2);
            *(__nv_bfloat162*)(row + 64 + c0) = __float22bfloat162_rn(m2);
        }
    }
}

// =====================================================================
// Kernel 3: fused edge aggregation + epilogue. One warp per dst node,
// TWO edges processed concurrently (16 lanes x 4 cols each).
// =====================================================================
__global__ __launch_bounds__(256) void layer_kernel(
    const float* __restrict__ hin, const float* __restrict__ q,
    const __nv_bfloat16* __restrict__ km,
    const int* __restrict__ off, const int* __restrict__ cnt,
    const int* __restrict__ csr,
    const float* __restrict__ prel,
    const float* __restrict__ Wo, const float* __restrict__ bo,
    const float* __restrict__ skp,
    float* __restrict__ hout, int n)
{
    __shared__ float sWo[64 * 64];
    {
        int t4 = threadIdx.x * 4;
#pragma unroll
        for (int i = 0; i < 4; i++) {
            int idx = t4 + i * 1024;
            *(float4*)&sWo[idx] = *(const float4*)&Wo[idx];
        }
    }
    __syncthreads();

    const int w    = threadIdx.x >> 5;
    const int lane = threadIdx.x & 31;
    const int node = blockIdx.x * 8 + w;
    if (node >= n) return;

    const int sub = lane >> 4;       // which of 2 concurrent edges
    const int sl  = lane & 15;       // lane within edge
    const int c0  = sl * 4;          // 4 cols per lane
    const int hd  = sl >> 2;
    const float pr = prel[hd] * 0.25f;   // 1/sqrt(16)

    const float4 qv = *(const float4*)&q[(size_t)node * 64 + c0];
    const int base = off[node];
    const int deg  = cnt[node];

    float4 acc = make_float4(0.f, 0.f, 0.f, 0.f);
    float wsum = 0.f;

    for (int i0 = 0; i0 < deg; i0 += 32) {
        int idx  = i0 + lane;
        int sreg = (idx < deg) ? csr[base + idx] : 0;
        int m = deg - i0; if (m > 32) m = 32;
#pragma unroll 4
        for (int jj = 0; jj < m; jj += 2) {
            int e  = jj + sub;
            bool ok = (e < m);
            int s = __shfl_sync(0xffffffffu, sreg, e);
            if (!ok) s = 0;
            const __nv_bfloat16* row = km + (size_t)s * 128;
            uint2 ku = *(const uint2*)(row + c0);
            uint2 mu = *(const uint2*)(row + 64 + c0);
            float2 k01 = __bfloat1622float2(*(const __nv_bfloat162*)&ku.x);
            float2 k23 = __bfloat1622float2(*(const __nv_bfloat162*)&ku.y);
            float2 m01 = __bfloat1622float2(*(const __nv_bfloat162*)&mu.x);
            float2 m23 = __bfloat1622float2(*(const __nv_bfloat162*)&mu.y);
            float p = k01.x * qv.x + k01.y * qv.y + k23.x * qv.z + k23.y * qv.w;
            p += __shfl_xor_sync(0xffffffffu, p, 1);
            p += __shfl_xor_sync(0xffffffffu, p, 2);
            float wgt = ok ? __expf(p * pr) : 0.f;
            acc.x = fmaf(wgt, m01.x, acc.x);
            acc.y = fmaf(wgt, m01.y, acc.y);
            acc.z = fmaf(wgt, m23.x, acc.z);
            acc.w = fmaf(wgt, m23.y, acc.w);
            wsum += wgt;
        }
    }

    // combine the two edge-halves (lanes i and i+16 hold partial sums)
    acc.x += __shfl_xor_sync(0xffffffffu, acc.x, 16);
    acc.y += __shfl_xor_sync(0xffffffffu, acc.y, 16);
    acc.z += __shfl_xor_sync(0xffffffffu, acc.z, 16);
    acc.w += __shfl_xor_sync(0xffffffffu, acc.w, 16);
    wsum  += __shfl_xor_sync(0xffffffffu, wsum, 16);

    const float inv = 1.0f / (wsum + 1e-16f);
    float4 g;
    g.x = gelu_tanh(acc.x * inv);
    g.y = gelu_tanh(acc.y * inv);
    g.z = gelu_tanh(acc.z * inv);
    g.w = gelu_tanh(acc.w * inv);

    // out = g @ Wo ; lane owns 2 output cols. g[j] lives on lane j>>2 (comp j&3).
    const int co2 = lane * 2;
    ull a = 0ull;
#pragma unroll
    for (int j4 = 0; j4 < 64; j4 += 4) {
        int jl = j4 >> 2;
        float g0 = __shfl_sync(0xffffffffu, g.x, jl);
        float g1 = __shfl_sync(0xffffffffu, g.y, jl);
        float g2 = __shfl_sync(0xffffffffu, g.z, jl);
        float g3 = __shfl_sync(0xffffffffu, g.w, jl);
        a = fma2(pack2(g0, g0), *(const ull*)&sWo[(j4    ) * 64 + co2], a);
        a = fma2(pack2(g1, g1), *(const ull*)&sWo[(j4 + 1) * 64 + co2], a);
        a = fma2(pack2(g2, g2), *(const ull*)&sWo[(j4 + 2) * 64 + co2], a);
        a = fma2(pack2(g3, g3), *(const ull*)&sWo[(j4 + 3) * 64 + co2], a);
    }

    const float sg = 1.0f / (1.0f + __expf(-skp[0]));
    float2 o = unpack2(a);
    o.x += bo[co2];
    o.y += bo[co2 + 1];
    float2 hp = *(const float2*)&hin[(size_t)node * 64 + co2];
    float r0 = fmaxf(sg * o.x + (1.0f - sg) * hp.x, 0.f);
    float r1 = fmaxf(sg * o.y + (1.0f - sg) * hp.y, 0.f);
    *(float2*)&hout[(size_t)node * 64 + co2] = make_float2(r0, r1);
}

// =====================================================================
// Kernel 4: classifier.  out = relu(h@Wc1+bc1) @ Wc2 + bc2
// =====================================================================
__global__ __launch_bounds__(256) void cls_kernel(
    const float* __restrict__ h,
    const float* __restrict__ Wc1, const float* __restrict__ bc1,
    const float* __restrict__ Wc2, const float* __restrict__ bc2,
    float* __restrict__ out, int n)
{
    const int w     = threadIdx.x >> 5;
    const int lane  = threadIdx.x & 31;
    const int node0 = (blockIdx.x * 8 + w) * 4;
    if (node0 >= n) return;
    const int c0 = lane * 2;

    float2 hv[4];
#pragma unroll
    for (int i = 0; i < 4; i++) {
        int nd = node0 + i;
        hv[i] = (nd < n) ? *(const float2*)&h[(size_t)nd * 64 + c0]
                         : make_float2(0.f, 0.f);
    }

    float acc[4] = {0.f, 0.f, 0.f, 0.f};
#pragma unroll 8
    for (int j = 0; j < 64; j += 2) {
        float w0 = Wc1[(j    ) * 32 + lane];
        float w1 = Wc1[(j + 1) * 32 + lane];
#pragma unroll
        for (int i = 0; i < 4; i++) {
            float h0 = __shfl_sync(0xffffffffu, hv[i].x, j >> 1);
            float h1 = __shfl_sync(0xffffffffu, hv[i].y, j >> 1);
            acc[i] = fmaf(h0, w0, acc[i]);
            acc[i] = fmaf(h1, w1, acc[i]);
        }
    }

    const float b1 = bc1[lane];
    float2 w2 = *(const float2*)&Wc2[lane * 2];
    const float bo0 = bc2[0], bo1 = bc2[1];
#pragma unroll
    for (int i = 0; i < 4; i++) {
        float hc = fmaxf(acc[i] + b1, 0.f);
        float o0 = hc * w2.x;
        float o1 = hc * w2.y;
#pragma unroll
        for (int m = 16; m >= 1; m >>= 1) {
            o0 += __shfl_xor_sync(0xffffffffu, o0, m);
            o1 += __shfl_xor_sync(0xffffffffu, o1, m);
        }
        int nd = node0 + i;
        if (lane == 0 && nd < n) {
            *(float2*)&out[(size_t)nd * 2] = make_float2(o0 + bo0, o1 + bo1);
        }
    }
}

// =====================================================================
extern "C" void kernel_launch(void* const* d_in, const int* in_sizes, int n_in,
                              void* d_out, int out_size)
{
    const float* x     = (const float*)d_in[0];
    const int*   ei    = (const int*)  d_in[1];
    const float* Wp    = (const float*)d_in[2];
    const float* bp    = (const float*)d_in[3];
    const float* Wk    = (const float*)d_in[4];
    const float* bk    = (const float*)d_in[5];
    const float* Wq    = (const float*)d_in[6];
    const float* bq    = (const float*)d_in[7];
    const float* Wv    = (const float*)d_in[8];
    const float* bv    = (const float*)d_in[9];
    const float* a_rel = (const float*)d_in[10];
    const float* m_rel = (const float*)d_in[11];
    const float* p_rel = (const float*)d_in[12];
    const float* Wo    = (const float*)d_in[13];
    const float* bo    = (const float*)d_in[14];
    const float* skp   = (const float*)d_in[15];
    const float* Wc1   = (const float*)d_in[16];
    const float* bc1   = (const float*)d_in[17];
    const float* Wc2   = (const float*)d_in[18];
    const float* bc2   = (const float*)d_in[19];

    const int n  = in_sizes[0] / 768;
    const int ne = in_sizes[1] / 2;

    float *h0, *h1, *qb;
    __nv_bfloat16 *kmb;
    int *cnt, *cnt2, *off, *part, *partScan, *part2, *csr;
    cudaGetSymbolAddress((void**)&h0,  g_h0);
    cudaGetSymbolAddress((void**)&h1,  g_h1);
    cudaGetSymbolAddress((void**)&qb,  g_q);
    cudaGetSymbolAddress((void**)&kmb, g_km);
    cudaGetSymbolAddress((void**)&cnt, g_cnt);
    cudaGetSymbolAddress((void**)&cnt2, g_cnt2);
    cudaGetSymbolAddress((void**)&off, g_off);
    cudaGetSymbolAddress((void**)&part, g_part);
    cudaGetSymbolAddress((void**)&partScan, g_partScan);
    cudaGetSymbolAddress((void**)&part2, g_part2);
    cudaGetSymbolAddress((void**)&csr, g_csr);

    const int gProj = (n + 127) / 128;
    const int gNode = (n + 31) / 32;
    const int gWarp = (n + 7) / 8;
    const int gE    = (ne + 255) / 256;
    const int nScanBlocks = (n + 1023) / 1024;

    // Launch order chosen so proj is launch #4 (ncu profiles launch #4).
    zero_kernel<<<(n + 255) / 256, 256>>>(cnt, cnt2, n);                  // 1
    hist_kernel<<<gE, 256>>>(ei, cnt, ne);                                 // 2
    scan1_kernel<<<nScanBlocks, 1024>>>(cnt, off, part, n);                // 3
    proj_kernel<<<gProj, 256>>>(x, Wp, bp, h0, n);                         // 4
    scan1_kernel<<<1, 1024>>>(part, partScan, part2, nScanBlocks);         // 5
    scan3_kernel<<<nScanBlocks, 1024>>>(off, partScan, n);                 // 6
    scatter_kernel<<<gE, 256>>>(ei, off, cnt2, csr, ne);                   // 7

    const float* hin = h0;
    float* hout = h1;
    for (int l = 0; l < 2; l++) {
        qkv_kernel<<<gNode, 256>>>(hin,
                                   Wk + l * 4096, bk + l * 64,
                                   Wq + l * 4096, bq + l * 64,
                                   Wv + l * 4096, bv + l * 64,
                                   a_rel + l * 1024, m_rel + l * 1024,
                                   qb, kmb, n);
        layer_kernel<<<gWarp, 256>>>(hin, qb, kmb, off, cnt, csr,
                                     p_rel + l * 4,
                                     Wo + l * 4096, bo + l * 64, skp + l,
                                     hout, n);
        const float* t = hin; hin = hout; hout = (float*)t;
    }

    cls_kernel<<<gNode, 256>>>(hin, Wc1, bc1, Wc2, bc2, (float*)d_out, n);
}

// round 5
// speedup vs baseline: 1.4652x; 1.2068x over previous
#include <cuda_runtime.h>
#include <cuda_bf16.h>
#include <cstdint>

typedef unsigned long long ull;

#define NMAX 100032
#define EMAX 1664000
#define HID 64

// ---------------- packed fp32x2 helpers ----------------
__device__ __forceinline__ ull fma2(ull a, ull b, ull c) {
    ull d;
    asm("fma.rn.f32x2 %0, %1, %2, %3;" : "=l"(d) : "l"(a), "l"(b), "l"(c));
    return d;
}
__device__ __forceinline__ ull pack2(float x, float y) {
    ull r; asm("mov.b64 %0, {%1, %2};" : "=l"(r) : "f"(x), "f"(y)); return r;
}
__device__ __forceinline__ float2 unpack2(ull v) {
    float2 r; asm("mov.b64 {%0, %1}, %2;" : "=f"(r.x), "=f"(r.y) : "l"(v)); return r;
}

__device__ __forceinline__ void cp16(void* smem, const void* gmem) {
    unsigned saddr = (unsigned)__cvta_generic_to_shared(smem);
    asm volatile("cp.async.cg.shared.global [%0], [%1], 16;" :: "r"(saddr), "l"(gmem));
}
__device__ __forceinline__ void cp_commit() { asm volatile("cp.async.commit_group;"); }
template <int N>
__device__ __forceinline__ void cp_wait() { asm volatile("cp.async.wait_group %0;" :: "n"(N)); }

__device__ __forceinline__ float gelu_tanh(float x) {
    float x3 = x * x * x;
    return 0.5f * x * (1.0f + tanhf(0.79788456080286535588f * (x + 0.044715f * x3)));
}

// bf16 mma (sm_80+; no 'a'-suffix arch features needed)
#define MMA_BF16(d, a0, a1, a2, a3, b0, b1) \
    asm volatile( \
        "mma.sync.aligned.m16n8k16.row.col.f32.bf16.bf16.f32 " \
        "{%0,%1,%2,%3},{%4,%5,%6,%7},{%8,%9},{%0,%1,%2,%3};" \
        : "+f"((d)[0]), "+f"((d)[1]), "+f"((d)[2]), "+f"((d)[3]) \
        : "r"(a0), "r"(a1), "r"(a2), "r"(a3), "r"(b0), "r"(b1))

__device__ __forceinline__ uint32_t f2_to_bf2(float2 v) {
    __nv_bfloat162 b = __float22bfloat162_rn(v);
    return *(uint32_t*)&b;
}
__device__ __forceinline__ float2 bf2_to_f2(uint32_t u) {
    return __bfloat1622float2(*(__nv_bfloat162*)&u);
}

// ---------------- scratch (device globals; no runtime alloc) ----------------
__device__ float g_h0 [NMAX * HID];
__device__ float g_h1 [NMAX * HID];
__device__ float g_q  [NMAX * HID];
__device__ __nv_bfloat16 g_km[NMAX * 128];
__device__ uint2 g_Bhi[48 * 8 * 32];    // W hi, mma B-fragment order
__device__ uint2 g_Blo[48 * 8 * 32];    // W lo
__device__ int   g_cnt [NMAX];
__device__ int   g_cnt2[NMAX];
__device__ int   g_off [NMAX];
__device__ int   g_part[128];
__device__ int   g_partScan[128];
__device__ int   g_part2[128];
__device__ int   g_csr [EMAX];

// =====================================================================
// W prep: split Wp (768x64) into bf16 hi/lo, packed in m16n8k16 B-frag
// order: idx = (t*8 + nt)*32 + lane ; uint2 = {b0, b1}.
//   b0 = W[kb, n], W[kb+1, n] ;  b1 = W[kb+8, n], W[kb+9, n]
//   kb = t*16 + tig*2 ; n = nt*8 + g ; g = lane>>2, tig = lane&3
// =====================================================================
__global__ void wprep_kernel(const float* __restrict__ Wp,
                             uint2* __restrict__ bhi, uint2* __restrict__ blo)
{
    int e = blockIdx.x * 256 + threadIdx.x;
    if (e >= 48 * 8 * 32) return;
    int lane = e & 31;
    int nt   = (e >> 5) & 7;
    int t    = e >> 8;
    int g = lane >> 2, tig = lane & 3;
    int nn = nt * 8 + g;
    int kb = t * 16 + tig * 2;

    float v00 = Wp[(kb    ) * 64 + nn];
    float v01 = Wp[(kb + 1) * 64 + nn];
    float v10 = Wp[(kb + 8) * 64 + nn];
    float v11 = Wp[(kb + 9) * 64 + nn];

    uint32_t h0 = f2_to_bf2(make_float2(v00, v01));
    uint32_t h1 = f2_to_bf2(make_float2(v10, v11));
    float2 hf0 = bf2_to_f2(h0), hf1 = bf2_to_f2(h1);
    uint32_t l0 = f2_to_bf2(make_float2(v00 - hf0.x, v01 - hf0.y));
    uint32_t l1 = f2_to_bf2(make_float2(v10 - hf1.x, v11 - hf1.y));

    bhi[e] = make_uint2(h0, h1);
    blo[e] = make_uint2(l0, l1);
}

// =====================================================================
// proj: h = x @ Wp + bp via bf16 3-term split on HMMA (mma.sync).
// BM=128, BN=64, k-chunks of 16, double-buffered cp.async.
// Warp w owns rows [16w, 16w+16), all 64 cols (8 ntiles).
// A smem: f32 pairs, slot = row*8 + (kp ^ ((row&3)<<1))  (conflict-free)
// =====================================================================
__device__ __forceinline__ int aswz(int row, int kp) {
    return row * 8 + (kp ^ ((row & 3) << 1));
}

__global__ __launch_bounds__(256) void proj_mma_kernel(
    const float* __restrict__ x, const float* __restrict__ bp,
    const uint2* __restrict__ gBhi, const uint2* __restrict__ gBlo,
    float* __restrict__ h, int n)
{
    __shared__ ull  sA[2][128 * 8];        // 8KB per buffer
    __shared__ uint2 sB[2][2][8][32];      // [buf][hi/lo][nt][lane], 4KB per buf

    const int tid  = threadIdx.x;
    const int gm   = blockIdx.x * 128;
    const int warp = tid >> 5, lane = tid & 31;
    const int g    = lane >> 2, tig = lane & 3;
    const int rA0  = warp * 16 + g;        // smem row for a0/a2
    const int rA1  = rA0 + 8;              // smem row for a1/a3

    auto prefetch = [&](int t) {
        int buf = t & 1;
#pragma unroll
        for (int i = 0; i < 2; i++) {
            int c = tid + i * 256;          // 0..511 : 16B chunks of A
            int row = c >> 2;
            int kp2 = (c & 3) * 2;          // even kp
            int slot = aswz(row, kp2);
            int grow = gm + row; if (grow >= n) grow = n - 1;
            cp16((char*)sA[buf] + slot * 8,
                 x + (size_t)grow * 768 + t * 16 + kp2 * 2);
        }
        {   // B: hi 2KB by threads 0-127, lo 2KB by threads 128-255
            int hl = tid >> 7;              // 0 or 1
            int c  = tid & 127;             // 16B chunk
            const uint2* src = hl ? gBlo : gBhi;
            cp16((char*)&sB[buf][hl][0][0] + c * 16,
                 (const char*)(src + t * 256) + c * 16);
        }
    };

    float acc[8][4];
#pragma unroll
    for (int i = 0; i < 8; i++)
#pragma unroll
        for (int j = 0; j < 4; j++) acc[i][j] = 0.f;

    prefetch(0);
    cp_commit();

    for (int t = 0; t < 48; t++) {
        if (t + 1 < 48) {
            prefetch(t + 1);
            cp_commit();
            cp_wait<1>();
        } else {
            cp_wait<0>();
        }
        __syncthreads();

        const int buf = t & 1;
        // A fragments: 4 conflict-free LDS.64, convert to bf16 hi/lo
        float2 v0 = unpack2(sA[buf][aswz(rA0, tig    )]);
        float2 v1 = unpack2(sA[buf][aswz(rA1, tig    )]);
        float2 v2 = unpack2(sA[buf][aswz(rA0, tig + 4)]);
        float2 v3 = unpack2(sA[buf][aswz(rA1, tig + 4)]);

        uint32_t ah0 = f2_to_bf2(v0), ah1 = f2_to_bf2(v1);
        uint32_t ah2 = f2_to_bf2(v2), ah3 = f2_to_bf2(v3);
        float2 h0 = bf2_to_f2(ah0), h1 = bf2_to_f2(ah1);
        float2 h2 = bf2_to_f2(ah2), h3 = bf2_to_f2(ah3);
        uint32_t al0 = f2_to_bf2(make_float2(v0.x - h0.x, v0.y - h0.y));
        uint32_t al1 = f2_to_bf2(make_float2(v1.x - h1.x, v1.y - h1.y));
        uint32_t al2 = f2_to_bf2(make_float2(v2.x - h2.x, v2.y - h2.y));
        uint32_t al3 = f2_to_bf2(make_float2(v3.x - h3.x, v3.y - h3.y));

#pragma unroll
        for (int nt = 0; nt < 8; nt++) {
            uint2 bh = sB[buf][0][nt][lane];
            uint2 bl = sB[buf][1][nt][lane];
            MMA_BF16(acc[nt], ah0, ah1, ah2, ah3, bh.x, bh.y);
            MMA_BF16(acc[nt], al0, al1, al2, al3, bh.x, bh.y);
            MMA_BF16(acc[nt], ah0, ah1, ah2, ah3, bl.x, bl.y);
        }
        __syncthreads();
    }

    // epilogue: thread holds rows (gm+16w+g) and (+8), cols nt*8+2*tig+{0,1}
    const int ro0 = gm + warp * 16 + g;
    const int ro1 = ro0 + 8;
#pragma unroll
    for (int nt = 0; nt < 8; nt++) {
        int col = nt * 8 + tig * 2;
        float2 bv = __ldg((const float2*)&bp[col]);
        if (ro0 < n)
            *(float2*)&h[(size_t)ro0 * 64 + col] =
                make_float2(acc[nt][0] + bv.x, acc[nt][1] + bv.y);
        if (ro1 < n)
            *(float2*)&h[(size_t)ro1 * 64 + col] =
                make_float2(acc[nt][2] + bv.x, acc[nt][3] + bv.y);
    }
}

// =====================================================================
// CSR construction
// =====================================================================
__global__ void zero_kernel(int* a, int* b, int n) {
    int i = blockIdx.x * blockDim.x + threadIdx.x;
    if (i < n) { a[i] = 0; b[i] = 0; }
}

__global__ void hist_kernel(const int* __restrict__ ei, int* __restrict__ cnt, int ne) {
    int e = blockIdx.x * blockDim.x + threadIdx.x;
    if (e < ne) atomicAdd(&cnt[ei[ne + e]], 1);
}

__global__ __launch_bounds__(1024) void scan1_kernel(
    const int* __restrict__ in, int* __restrict__ out, int* __restrict__ part, int n)
{
    __shared__ int wsum[32];
    int t = threadIdx.x;
    int i = blockIdx.x * 1024 + t;
    int v = (i < n) ? in[i] : 0;
    int x = v;
#pragma unroll
    for (int d = 1; d < 32; d <<= 1) {
        int y = __shfl_up_sync(0xffffffffu, x, d);
        if ((t & 31) >= d) x += y;
    }
    if ((t & 31) == 31) wsum[t >> 5] = x;
    __syncthreads();
    if (t < 32) {
        int s = wsum[t];
        int sx = s;
#pragma unroll
        for (int d = 1; d < 32; d <<= 1) {
            int y = __shfl_up_sync(0xffffffffu, sx, d);
            if (t >= d) sx += y;
        }
        wsum[t] = sx - s;
    }
    __syncthreads();
    int excl = x - v + wsum[t >> 5];
    if (i < n) out[i] = excl;
    if (t == 1023 && part) part[blockIdx.x] = x + wsum[31];
}

__global__ void scan3_kernel(int* __restrict__ off, const int* __restrict__ partScan, int n) {
    int i = blockIdx.x * 1024 + threadIdx.x;
    if (i < n) off[i] += partScan[blockIdx.x];
}

__global__ void scatter_kernel(const int* __restrict__ ei,
                               const int* __restrict__ off, int* __restrict__ cnt2,
                               int* __restrict__ csr, int ne)
{
    int e = blockIdx.x * blockDim.x + threadIdx.x;
    if (e < ne) {
        int s = ei[e];
        int d = ei[ne + e];
        int pos = off[d] + atomicAdd(&cnt2[d], 1);
        csr[pos] = s;
    }
}

// =====================================================================
// qkv: per-node QKV + relation transforms
// =====================================================================
__global__ __launch_bounds__(256) void qkv_kernel(
    const float* __restrict__ h,
    const float* __restrict__ Wk, const float* __restrict__ bk,
    const float* __restrict__ Wq, const float* __restrict__ bq,
    const float* __restrict__ Wv, const float* __restrict__ bv,
    const float* __restrict__ Ar, const float* __restrict__ Mr,
    float* __restrict__ qo, __nv_bfloat16* __restrict__ kmo, int n)
{
    __shared__ float kbuf[8][4][64];
    __shared__ float vbuf[8][4][64];

    const int w     = threadIdx.x >> 5;
    const int lane  = threadIdx.x & 31;
    const int node0 = (blockIdx.x * 8 + w) * 4;
    if (node0 >= n) return;
    const int c0 = lane * 2;

    float2 hv[4];
#pragma unroll
    for (int i = 0; i < 4; i++) {
        int nd = node0 + i;
        hv[i] = (nd < n) ? *(const float2*)&h[(size_t)nd * 64 + c0]
                         : make_float2(0.f, 0.f);
    }

    ull ka[4] = {0,0,0,0}, qa[4] = {0,0,0,0}, va[4] = {0,0,0,0};
#pragma unroll 8
    for (int j = 0; j < 64; j += 2) {
        ull wk0 = *(const ull*)&Wk[(j    ) * 64 + c0];
        ull wq0 = *(const ull*)&Wq[(j    ) * 64 + c0];
        ull wv0 = *(const ull*)&Wv[(j    ) * 64 + c0];
        ull wk1 = *(const ull*)&Wk[(j + 1) * 64 + c0];
        ull wq1 = *(const ull*)&Wq[(j + 1) * 64 + c0];
        ull wv1 = *(const ull*)&Wv[(j + 1) * 64 + c0];
#pragma unroll
        for (int i = 0; i < 4; i++) {
            float h0 = __shfl_sync(0xffffffffu, hv[i].x, j >> 1);
            float h1 = __shfl_sync(0xffffffffu, hv[i].y, j >> 1);
            ull a0 = pack2(h0, h0);
            ull a1 = pack2(h1, h1);
            ka[i] = fma2(a0, wk0, ka[i]); ka[i] = fma2(a1, wk1, ka[i]);
            qa[i] = fma2(a0, wq0, qa[i]); qa[i] = fma2(a1, wq1, qa[i]);
            va[i] = fma2(a0, wv0, va[i]); va[i] = fma2(a1, wv1, va[i]);
        }
    }

    const float bk0 = bk[c0], bk1 = bk[c0 + 1];
    const float bq0 = bq[c0], bq1 = bq[c0 + 1];
    const float bv0 = bv[c0], bv1 = bv[c0 + 1];
#pragma unroll
    for (int i = 0; i < 4; i++) {
        float2 kk = unpack2(ka[i]); kk.x += bk0; kk.y += bk1;
        float2 qq = unpack2(qa[i]); qq.x += bq0; qq.y += bq1;
        float2 vv = unpack2(va[i]); vv.x += bv0; vv.y += bv1;
        int nd = node0 + i;
        if (nd < n) *(float2*)&qo[(size_t)nd * 64 + c0] = qq;
        kbuf[w][i][c0] = kk.x; kbuf[w][i][c0 + 1] = kk.y;
        vbuf[w][i][c0] = vv.x; vbuf[w][i][c0 + 1] = vv.y;
    }
    __syncwarp();

    const int hd = lane >> 3;
    const int f0 = c0 & 15;
    const float* Arh = Ar + hd * 256;
    const float* Mrh = Mr + hd * 256;
    ull kt[4] = {0,0,0,0}, mt[4] = {0,0,0,0};
#pragma unroll
    for (int d = 0; d < 16; d++) {
        ull ar = *(const ull*)&Arh[d * 16 + f0];
        ull mr = *(const ull*)&Mrh[d * 16 + f0];
#pragma unroll
        for (int i = 0; i < 4; i++) {
            float ks = kbuf[w][i][(hd << 4) + d];
            float vs = vbuf[w][i][(hd << 4) + d];
            kt[i] = fma2(pack2(ks, ks), ar, kt[i]);
            mt[i] = fma2(pack2(vs, vs), mr, mt[i]);
        }
    }

#pragma unroll
    for (int i = 0; i < 4; i++) {
        int nd = node0 + i;
        if (nd < n) {
            float2 k2 = unpack2(kt[i]);
            float2 m2 = unpack2(mt[i]);
            __nv_bfloat16* row = kmo + (size_t)nd * 128;
            *(__nv_bfloat162*)(row + c0)      = __float22bfloat162_rn(k2);
            *(__nv_bfloat162*)(row + 64 + c0) = __float22bfloat162_rn(m2);
        }
    }
}

// =====================================================================
// layer: fused edge aggregation + epilogue (warp per dst, 2 edges/warp)
// =====================================================================
__global__ __launch_bounds__(256) void layer_kernel(
    const float* __restrict__ hin, const float* __restrict__ q,
    const __nv_bfloat16* __restrict__ km,
    const int* __restrict__ off, const int* __restrict__ cnt,
    const int* __restrict__ csr,
    const float* __restrict__ prel,
    const float* __restrict__ Wo, const float* __restrict__ bo,
    const float* __restrict__ skp,
    float* __restrict__ hout, int n)
{
    __shared__ float sWo[64 * 64];
    {
        int t4 = threadIdx.x * 4;
#pragma unroll
        for (int i = 0; i < 4; i++) {
            int idx = t4 + i * 1024;
            *(float4*)&sWo[idx] = *(const float4*)&Wo[idx];
        }
    }
    __syncthreads();

    const int w    = threadIdx.x >> 5;
    const int lane = threadIdx.x & 31;
    const int node = blockIdx.x * 8 + w;
    if (node >= n) return;

    const int sub = lane >> 4;
    const int sl  = lane & 15;
    const int c0  = sl * 4;
    const int hd  = sl >> 2;
    const float pr = prel[hd] * 0.25f;

    const float4 qv = *(const float4*)&q[(size_t)node * 64 + c0];
    const int base = off[node];
    const int deg  = cnt[node];

    float4 acc = make_float4(0.f, 0.f, 0.f, 0.f);
    float wsum = 0.f;

    for (int i0 = 0; i0 < deg; i0 += 32) {
        int idx  = i0 + lane;
        int sreg = (idx < deg) ? csr[base + idx] : 0;
        int m = deg - i0; if (m > 32) m = 32;
#pragma unroll 4
        for (int jj = 0; jj < m; jj += 2) {
            int e  = jj + sub;
            bool ok = (e < m);
            int s = __shfl_sync(0xffffffffu, sreg, e);
            if (!ok) s = 0;
            const __nv_bfloat16* row = km + (size_t)s * 128;
            uint2 ku = *(const uint2*)(row + c0);
            uint2 mu = *(const uint2*)(row + 64 + c0);
            float2 k01 = __bfloat1622float2(*(const __nv_bfloat162*)&ku.x);
            float2 k23 = __bfloat1622float2(*(const __nv_bfloat162*)&ku.y);
            float2 m01 = __bfloat1622float2(*(const __nv_bfloat162*)&mu.x);
            float2 m23 = __bfloat1622float2(*(const __nv_bfloat162*)&mu.y);
            float p = k01.x * qv.x + k01.y * qv.y + k23.x * qv.z + k23.y * qv.w;
            p += __shfl_xor_sync(0xffffffffu, p, 1);
            p += __shfl_xor_sync(0xffffffffu, p, 2);
            float wgt = ok ? __expf(p * pr) : 0.f;
            acc.x = fmaf(wgt, m01.x, acc.x);
            acc.y = fmaf(wgt, m01.y, acc.y);
            acc.z = fmaf(wgt, m23.x, acc.z);
            acc.w = fmaf(wgt, m23.y, acc.w);
            wsum += wgt;
        }
    }

    acc.x += __shfl_xor_sync(0xffffffffu, acc.x, 16);
    acc.y += __shfl_xor_sync(0xffffffffu, acc.y, 16);
    acc.z += __shfl_xor_sync(0xffffffffu, acc.z, 16);
    acc.w += __shfl_xor_sync(0xffffffffu, acc.w, 16);
    wsum  += __shfl_xor_sync(0xffffffffu, wsum, 16);

    const float inv = 1.0f / (wsum + 1e-16f);
    float4 g;
    g.x = gelu_tanh(acc.x * inv);
    g.y = gelu_tanh(acc.y * inv);
    g.z = gelu_tanh(acc.z * inv);
    g.w = gelu_tanh(acc.w * inv);

    const int co2 = lane * 2;
    ull a = 0ull;
#pragma unroll
    for (int j4 = 0; j4 < 64; j4 += 4) {
        int jl = j4 >> 2;
        float g0 = __shfl_sync(0xffffffffu, g.x, jl);
        float g1 = __shfl_sync(0xffffffffu, g.y, jl);
        float g2 = __shfl_sync(0xffffffffu, g.z, jl);
        float g3 = __shfl_sync(0xffffffffu, g.w, jl);
        a = fma2(pack2(g0, g0), *(const ull*)&sWo[(j4    ) * 64 + co2], a);
        a = fma2(pack2(g1, g1), *(const ull*)&sWo[(j4 + 1) * 64 + co2], a);
        a = fma2(pack2(g2, g2), *(const ull*)&sWo[(j4 + 2) * 64 + co2], a);
        a = fma2(pack2(g3, g3), *(const ull*)&sWo[(j4 + 3) * 64 + co2], a);
    }

    const float sg = 1.0f / (1.0f + __expf(-skp[0]));
    float2 o = unpack2(a);
    o.x += bo[co2];
    o.y += bo[co2 + 1];
    float2 hp = *(const float2*)&hin[(size_t)node * 64 + co2];
    float r0 = fmaxf(sg * o.x + (1.0f - sg) * hp.x, 0.f);
    float r1 = fmaxf(sg * o.y + (1.0f - sg) * hp.y, 0.f);
    *(float2*)&hout[(size_t)node * 64 + co2] = make_float2(r0, r1);
}

// =====================================================================
// classifier
// =====================================================================
__global__ __launch_bounds__(256) void cls_kernel(
    const float* __restrict__ h,
    const float* __restrict__ Wc1, const float* __restrict__ bc1,
    const float* __restrict__ Wc2, const float* __restrict__ bc2,
    float* __restrict__ out, int n)
{
    const int w     = threadIdx.x >> 5;
    const int lane  = threadIdx.x & 31;
    const int node0 = (blockIdx.x * 8 + w) * 4;
    if (node0 >= n) return;
    const int c0 = lane * 2;

    float2 hv[4];
#pragma unroll
    for (int i = 0; i < 4; i++) {
        int nd = node0 + i;
        hv[i] = (nd < n) ? *(const float2*)&h[(size_t)nd * 64 + c0]
                         : make_float2(0.f, 0.f);
    }

    float acc[4] = {0.f, 0.f, 0.f, 0.f};
#pragma unroll 8
    for (int j = 0; j < 64; j += 2) {
        float w0 = Wc1[(j    ) * 32 + lane];
        float w1 = Wc1[(j + 1) * 32 + lane];
#pragma unroll
        for (int i = 0; i < 4; i++) {
            float h0 = __shfl_sync(0xffffffffu, hv[i].x, j >> 1);
            float h1 = __shfl_sync(0xffffffffu, hv[i].y, j >> 1);
            acc[i] = fmaf(h0, w0, acc[i]);
            acc[i] = fmaf(h1, w1, acc[i]);
        }
    }

    const float b1 = bc1[lane];
    float2 w2 = *(const float2*)&Wc2[lane * 2];
    const float bo0 = bc2[0], bo1 = bc2[1];
#pragma unroll
    for (int i = 0; i < 4; i++) {
        float hc = fmaxf(acc[i] + b1, 0.f);
        float o0 = hc * w2.x;
        float o1 = hc * w2.y;
#pragma unroll
        for (int m = 16; m >= 1; m >>= 1) {
            o0 += __shfl_xor_sync(0xffffffffu, o0, m);
            o1 += __shfl_xor_sync(0xffffffffu, o1, m);
        }
        int nd = node0 + i;
        if (lane == 0 && nd < n) {
            *(float2*)&out[(size_t)nd * 2] = make_float2(o0 + bo0, o1 + bo1);
        }
    }
}

// =====================================================================
extern "C" void kernel_launch(void* const* d_in, const int* in_sizes, int n_in,
                              void* d_out, int out_size)
{
    const float* x     = (const float*)d_in[0];
    const int*   ei    = (const int*)  d_in[1];
    const float* Wp    = (const float*)d_in[2];
    const float* bp    = (const float*)d_in[3];
    const float* Wk    = (const float*)d_in[4];
    const float* bk    = (const float*)d_in[5];
    const float* Wq    = (const float*)d_in[6];
    const float* bq    = (const float*)d_in[7];
    const float* Wv    = (const float*)d_in[8];
    const float* bv    = (const float*)d_in[9];
    const float* a_rel = (const float*)d_in[10];
    const float* m_rel = (const float*)d_in[11];
    const float* p_rel = (const float*)d_in[12];
    const float* Wo    = (const float*)d_in[13];
    const float* bo    = (const float*)d_in[14];
    const float* skp   = (const float*)d_in[15];
    const float* Wc1   = (const float*)d_in[16];
    const float* bc1   = (const float*)d_in[17];
    const float* Wc2   = (const float*)d_in[18];
    const float* bc2   = (const float*)d_in[19];

    const int n  = in_sizes[0] / 768;
    const int ne = in_sizes[1] / 2;

    float *h0, *h1, *qb;
    __nv_bfloat16 *kmb;
    uint2 *bhi, *blo;
    int *cnt, *cnt2, *off, *part, *partScan, *part2, *csr;
    cudaGetSymbolAddress((void**)&h0,  g_h0);
    cudaGetSymbolAddress((void**)&h1,  g_h1);
    cudaGetSymbolAddress((void**)&qb,  g_q);
    cudaGetSymbolAddress((void**)&kmb, g_km);
    cudaGetSymbolAddress((void**)&bhi, g_Bhi);
    cudaGetSymbolAddress((void**)&blo, g_Blo);
    cudaGetSymbolAddress((void**)&cnt, g_cnt);
    cudaGetSymbolAddress((void**)&cnt2, g_cnt2);
    cudaGetSymbolAddress((void**)&off, g_off);
    cudaGetSymbolAddress((void**)&part, g_part);
    cudaGetSymbolAddress((void**)&partScan, g_partScan);
    cudaGetSymbolAddress((void**)&part2, g_part2);
    cudaGetSymbolAddress((void**)&csr, g_csr);

    const int gProj = (n + 127) / 128;
    const int gNode = (n + 31) / 32;
    const int gWarp = (n + 7) / 8;
    const int gE    = (ne + 255) / 256;
    const int nScanBlocks = (n + 1023) / 1024;

    // Launch order: qkv at slot #4 (ncu profiles launch #4).
    wprep_kernel<<<48, 256>>>(Wp, bhi, blo);                                 // 1
    proj_mma_kernel<<<gProj, 256>>>(x, bp, bhi, blo, h0, n);                 // 2
    zero_kernel<<<(n + 255) / 256, 256>>>(cnt, cnt2, n);                     // 3
    qkv_kernel<<<gNode, 256>>>(h0, Wk, bk, Wq, bq, Wv, bv,                   // 4
                               a_rel, m_rel, qb, kmb, n);
    hist_kernel<<<gE, 256>>>(ei, cnt, ne);                                    // 5
    scan1_kernel<<<nScanBlocks, 1024>>>(cnt, off, part, n);                   // 6
    scan1_kernel<<<1, 1024>>>(part, partScan, part2, nScanBlocks);            // 7
    scan3_kernel<<<nScanBlocks, 1024>>>(off, partScan, n);                    // 8
    scatter_kernel<<<gE, 256>>>(ei, off, cnt2, csr, ne);                      // 9

    layer_kernel<<<gWarp, 256>>>(h0, qb, kmb, off, cnt, csr,                  // 10
                                 p_rel, Wo, bo, skp, h1, n);
    qkv_kernel<<<gNode, 256>>>(h1,                                            // 11
                               Wk + 4096, bk + 64, Wq + 4096, bq + 64,
                               Wv + 4096, bv + 64,
                               a_rel + 1024, m_rel + 1024, qb, kmb, n);
    layer_kernel<<<gWarp, 256>>>(h1, qb, kmb, off, cnt, csr,                  // 12
                                 p_rel + 4, Wo + 4096, bo + 64, skp + 1,
                                 h0, n);

    cls_kernel<<<gNode, 256>>>(h0, Wc1, bc1, Wc2, bc2, (float*)d_out, n);     // 13
}

// round 6
// speedup vs baseline: 1.7496x; 1.1941x over previous
#include <cuda_runtime.h>
#include <cuda_bf16.h>
#include <cstdint>

typedef unsigned long long ull;

#define NMAX 100032
#define EMAX 1664000
#define HID 64

// ---------------- packed fp32x2 helpers ----------------
__device__ __forceinline__ ull fma2(ull a, ull b, ull c) {
    ull d;
    asm("fma.rn.f32x2 %0, %1, %2, %3;" : "=l"(d) : "l"(a), "l"(b), "l"(c));
    return d;
}
__device__ __forceinline__ ull pack2(float x, float y) {
    ull r; asm("mov.b64 %0, {%1, %2};" : "=l"(r) : "f"(x), "f"(y)); return r;
}
__device__ __forceinline__ float2 unpack2(ull v) {
    float2 r; asm("mov.b64 {%0, %1}, %2;" : "=f"(r.x), "=f"(r.y) : "l"(v)); return r;
}

__device__ __forceinline__ void cp16(void* smem, const void* gmem) {
    unsigned saddr = (unsigned)__cvta_generic_to_shared(smem);
    asm volatile("cp.async.cg.shared.global [%0], [%1], 16;" :: "r"(saddr), "l"(gmem));
}
__device__ __forceinline__ void cp_commit() { asm volatile("cp.async.commit_group;"); }
template <int N>
__device__ __forceinline__ void cp_wait() { asm volatile("cp.async.wait_group %0;" :: "n"(N)); }

__device__ __forceinline__ float gelu_tanh(float x) {
    float x3 = x * x * x;
    return 0.5f * x * (1.0f + tanhf(0.79788456080286535588f * (x + 0.044715f * x3)));
}

// bf16 mma (sm_80+)
#define MMA_BF16(d, a0, a1, a2, a3, b0, b1) \
    asm volatile( \
        "mma.sync.aligned.m16n8k16.row.col.f32.bf16.bf16.f32 " \
        "{%0,%1,%2,%3},{%4,%5,%6,%7},{%8,%9},{%0,%1,%2,%3};" \
        : "+f"((d)[0]), "+f"((d)[1]), "+f"((d)[2]), "+f"((d)[3]) \
        : "r"(a0), "r"(a1), "r"(a2), "r"(a3), "r"(b0), "r"(b1))

__device__ __forceinline__ uint32_t f2_to_bf2(float2 v) {
    __nv_bfloat162 b = __float22bfloat162_rn(v);
    return *(uint32_t*)&b;
}
__device__ __forceinline__ float2 bf2_to_f2(uint32_t u) {
    return __bfloat1622float2(*(__nv_bfloat162*)&u);
}

// ---------------- scratch ----------------
__device__ float g_h0 [NMAX * HID];
__device__ float g_h1 [NMAX * HID];
__device__ __nv_bfloat16 g_qb[NMAX * 64];
__device__ __nv_bfloat16 g_km[NMAX * 128];   // [kT'(64) | mT(64)] per node
__device__ uint2 g_Bhi[48 * 8 * 32];         // proj W hi frag images
__device__ uint2 g_Blo[48 * 8 * 32];
__device__ uint2 g_Chi[2 * 4 * 24 * 32];     // combined qkv W frag images (2 layers)
__device__ uint2 g_Clo[2 * 4 * 24 * 32];
__device__ float g_bc [2 * 192];             // combined biases
__device__ int   g_cnt [NMAX];
__device__ int   g_cnt2[NMAX];
__device__ int   g_off [NMAX];
__device__ int   g_part[128];
__device__ int   g_partScan[128];
__device__ int   g_part2[128];
__device__ int   g_csr [EMAX];

// =====================================================================
// W prep for proj (768x64 -> bf16 hi/lo m16n8k16 B-frag order)
// =====================================================================
__global__ void wprep_kernel(const float* __restrict__ Wp,
                             uint2* __restrict__ bhi, uint2* __restrict__ blo)
{
    int e = blockIdx.x * 256 + threadIdx.x;
    if (e >= 48 * 8 * 32) return;
    int lane = e & 31;
    int nt   = (e >> 5) & 7;
    int t    = e >> 8;
    int g = lane >> 2, tig = lane & 3;
    int nn = nt * 8 + g;
    int kb = t * 16 + tig * 2;

    float v00 = Wp[(kb    ) * 64 + nn];
    float v01 = Wp[(kb + 1) * 64 + nn];
    float v10 = Wp[(kb + 8) * 64 + nn];
    float v11 = Wp[(kb + 9) * 64 + nn];

    uint32_t h0 = f2_to_bf2(make_float2(v00, v01));
    uint32_t h1 = f2_to_bf2(make_float2(v10, v11));
    float2 hf0 = bf2_to_f2(h0), hf1 = bf2_to_f2(h1);
    uint32_t l0 = f2_to_bf2(make_float2(v00 - hf0.x, v01 - hf0.y));
    uint32_t l1 = f2_to_bf2(make_float2(v10 - hf1.x, v11 - hf1.y));

    bhi[e] = make_uint2(h0, h1);
    blo[e] = make_uint2(l0, l1);
}

// =====================================================================
// Combined qkv weights: Wc[64][192] = [Wq | WkT*pr | WvM] per layer,
// packed directly into bf16 hi/lo B-frag images. Also combined biases.
//   WkT[j, h*16+f] = sum_d Wk[j, h*16+d] * a_rel[h,d,f]  (xp_rel[h]/4)
//   WvM[j, h*16+f] = sum_d Wv[j, h*16+d] * m_rel[h,d,f]
// =====================================================================
__device__ float wc_val(int l, int j, int c,
                        const float* Wk, const float* Wq, const float* Wv,
                        const float* Ar, const float* Mr, const float* prel)
{
    if (c < 64) return Wq[l * 4096 + j * 64 + c];
    if (c < 128) {
        int f = c - 64, hh = f >> 4, fi = f & 15;
        float s = 0.f;
#pragma unroll
        for (int d = 0; d < 16; d++)
            s += Wk[l * 4096 + j * 64 + hh * 16 + d] * Ar[l * 1024 + hh * 256 + d * 16 + fi];
        return s * (prel[l * 4 + hh] * 0.25f);
    }
    int f = c - 128, hh = f >> 4, fi = f & 15;
    float s = 0.f;
#pragma unroll
    for (int d = 0; d < 16; d++)
        s += Wv[l * 4096 + j * 64 + hh * 16 + d] * Mr[l * 1024 + hh * 256 + d * 16 + fi];
    return s;
}

__global__ void wcombpack_kernel(
    const float* __restrict__ Wk, const float* __restrict__ bk,
    const float* __restrict__ Wq, const float* __restrict__ bq,
    const float* __restrict__ Wv, const float* __restrict__ bv,
    const float* __restrict__ Ar, const float* __restrict__ Mr,
    const float* __restrict__ prel,
    uint2* __restrict__ chi, uint2* __restrict__ clo, float* __restrict__ bc)
{
    int e = blockIdx.x * 256 + threadIdx.x;
    if (e < 6144) {
        int lane = e & 31;
        int r    = e >> 5;          // 0..191
        int nt   = r % 24;
        int r2   = r / 24;          // 0..7
        int ch   = r2 & 3;
        int l    = r2 >> 2;
        int g = lane >> 2, tig = lane & 3;
        int nn = nt * 8 + g;
        int kb = ch * 16 + tig * 2;

        float v00 = wc_val(l, kb,     nn, Wk, Wq, Wv, Ar, Mr, prel);
        float v01 = wc_val(l, kb + 1, nn, Wk, Wq, Wv, Ar, Mr, prel);
        float v10 = wc_val(l, kb + 8, nn, Wk, Wq, Wv, Ar, Mr, prel);
        float v11 = wc_val(l, kb + 9, nn, Wk, Wq, Wv, Ar, Mr, prel);

        uint32_t h0 = f2_to_bf2(make_float2(v00, v01));
        uint32_t h1 = f2_to_bf2(make_float2(v10, v11));
        float2 hf0 = bf2_to_f2(h0), hf1 = bf2_to_f2(h1);
        uint32_t l0 = f2_to_bf2(make_float2(v00 - hf0.x, v01 - hf0.y));
        uint32_t l1 = f2_to_bf2(make_float2(v10 - hf1.x, v11 - hf1.y));
        chi[e] = make_uint2(h0, h1);
        clo[e] = make_uint2(l0, l1);
    } else if (e < 6144 + 384) {
        int e2 = e - 6144;
        int l = e2 / 192, c = e2 % 192;
        float v;
        if (c < 64) {
            v = bq[l * 64 + c];
        } else if (c < 128) {
            int f = c - 64, hh = f >> 4, fi = f & 15;
            float s = 0.f;
#pragma unroll
            for (int d = 0; d < 16; d++)
                s += bk[l * 64 + hh * 16 + d] * Ar[l * 1024 + hh * 256 + d * 16 + fi];
            v = s * (prel[l * 4 + hh] * 0.25f);
        } else {
            int f = c - 128, hh = f >> 4, fi = f & 15;
            float s = 0.f;
#pragma unroll
            for (int d = 0; d < 16; d++)
                s += bv[l * 64 + hh * 16 + d] * Mr[l * 1024 + hh * 256 + d * 16 + fi];
            v = s;
        }
        bc[e2] = v;
    }
}

// =====================================================================
// proj: h = x @ Wp + bp via bf16 3-term split HMMA (from R5, unchanged)
// =====================================================================
__device__ __forceinline__ int aswz(int row, int kp) {
    return row * 8 + (kp ^ ((row & 3) << 1));
}

__global__ __launch_bounds__(256) void proj_mma_kernel(
    const float* __restrict__ x, const float* __restrict__ bp,
    const uint2* __restrict__ gBhi, const uint2* __restrict__ gBlo,
    float* __restrict__ h, int n)
{
    __shared__ ull  sA[2][128 * 8];
    __shared__ uint2 sB[2][2][8][32];

    const int tid  = threadIdx.x;
    const int gm   = blockIdx.x * 128;
    const int warp = tid >> 5, lane = tid & 31;
    const int g    = lane >> 2, tig = lane & 3;
    const int rA0  = warp * 16 + g;
    const int rA1  = rA0 + 8;

    auto prefetch = [&](int t) {
        int buf = t & 1;
#pragma unroll
        for (int i = 0; i < 2; i++) {
            int c = tid + i * 256;
            int row = c >> 2;
            int kp2 = (c & 3) * 2;
            int slot = aswz(row, kp2);
            int grow = gm + row; if (grow >= n) grow = n - 1;
            cp16((char*)sA[buf] + slot * 8,
                 x + (size_t)grow * 768 + t * 16 + kp2 * 2);
        }
        {
            int hl = tid >> 7;
            int c  = tid & 127;
            const uint2* src = hl ? gBlo : gBhi;
            cp16((char*)&sB[buf][hl][0][0] + c * 16,
                 (const char*)(src + t * 256) + c * 16);
        }
    };

    float acc[8][4];
#pragma unroll
    for (int i = 0; i < 8; i++)
#pragma unroll
        for (int j = 0; j < 4; j++) acc[i][j] = 0.f;

    prefetch(0);
    cp_commit();

    for (int t = 0; t < 48; t++) {
        if (t + 1 < 48) {
            prefetch(t + 1);
            cp_commit();
            cp_wait<1>();
        } else {
            cp_wait<0>();
        }
        __syncthreads();

        const int buf = t & 1;
        float2 v0 = unpack2(sA[buf][aswz(rA0, tig    )]);
        float2 v1 = unpack2(sA[buf][aswz(rA1, tig    )]);
        float2 v2 = unpack2(sA[buf][aswz(rA0, tig + 4)]);
        float2 v3 = unpack2(sA[buf][aswz(rA1, tig + 4)]);

        uint32_t ah0 = f2_to_bf2(v0), ah1 = f2_to_bf2(v1);
        uint32_t ah2 = f2_to_bf2(v2), ah3 = f2_to_bf2(v3);
        float2 h0 = bf2_to_f2(ah0), h1 = bf2_to_f2(ah1);
        float2 h2 = bf2_to_f2(ah2), h3 = bf2_to_f2(ah3);
        uint32_t al0 = f2_to_bf2(make_float2(v0.x - h0.x, v0.y - h0.y));
        uint32_t al1 = f2_to_bf2(make_float2(v1.x - h1.x, v1.y - h1.y));
        uint32_t al2 = f2_to_bf2(make_float2(v2.x - h2.x, v2.y - h2.y));
        uint32_t al3 = f2_to_bf2(make_float2(v3.x - h3.x, v3.y - h3.y));

#pragma unroll
        for (int nt = 0; nt < 8; nt++) {
            uint2 bh = sB[buf][0][nt][lane];
            uint2 bl = sB[buf][1][nt][lane];
            MMA_BF16(acc[nt], ah0, ah1, ah2, ah3, bh.x, bh.y);
            MMA_BF16(acc[nt], al0, al1, al2, al3, bh.x, bh.y);
            MMA_BF16(acc[nt], ah0, ah1, ah2, ah3, bl.x, bl.y);
        }
        __syncthreads();
    }

    const int ro0 = gm + warp * 16 + g;
    const int ro1 = ro0 + 8;
#pragma unroll
    for (int nt = 0; nt < 8; nt++) {
        int col = nt * 8 + tig * 2;
        float2 bv = __ldg((const float2*)&bp[col]);
        if (ro0 < n)
            *(float2*)&h[(size_t)ro0 * 64 + col] =
                make_float2(acc[nt][0] + bv.x, acc[nt][1] + bv.y);
        if (ro1 < n)
            *(float2*)&h[(size_t)ro1 * 64 + col] =
                make_float2(acc[nt][2] + bv.x, acc[nt][3] + bv.y);
    }
}

// =====================================================================
// qkv (HMMA): [q | kT' | mT](n x 192) = h(n x 64) @ Wc + bc, bf16 out.
// BM=128, 512 threads (16 warps). Warp (rowg, colh): rows rowg*16..+16,
// cols colh*96..+96 (12 ntiles). K = 4 chunks of 16.
// =====================================================================
__global__ __launch_bounds__(512) void qkv_mma_kernel(
    const float* __restrict__ h,
    const uint2* __restrict__ gChi, const uint2* __restrict__ gClo,
    const float* __restrict__ bc,
    __nv_bfloat16* __restrict__ qo, __nv_bfloat16* __restrict__ kmo,
    int n, int l)
{
    __shared__ uint2 sBh[4][24][32];
    __shared__ uint2 sBl[4][24][32];

    const int tid = threadIdx.x;
    {
        const uint4* srch = (const uint4*)(gChi + l * 3072);
        const uint4* srcl = (const uint4*)(gClo + l * 3072);
        uint4* dh = (uint4*)sBh;
        uint4* dl = (uint4*)sBl;
#pragma unroll
        for (int i = 0; i < 3; i++) {
            dh[tid + i * 512] = srch[tid + i * 512];
            dl[tid + i * 512] = srcl[tid + i * 512];
        }
    }
    __syncthreads();

    const int warp = tid >> 5, lane = tid & 31;
    const int g = lane >> 2, tig = lane & 3;
    const int rowg = warp >> 1, colh = warp & 1;
    const int gm = blockIdx.x * 128;
    const int r0 = gm + rowg * 16 + g;
    const int r1 = r0 + 8;
    const int r0c = (r0 < n) ? r0 : n - 1;
    const int r1c = (r1 < n) ? r1 : n - 1;

    float acc[12][4];
#pragma unroll
    for (int i = 0; i < 12; i++)
#pragma unroll
        for (int j = 0; j < 4; j++) acc[i][j] = 0.f;

#pragma unroll
    for (int ch = 0; ch < 4; ch++) {
        int co = ch * 16 + tig * 2;
        float2 v0 = *(const float2*)&h[(size_t)r0c * 64 + co];
        float2 v1 = *(const float2*)&h[(size_t)r1c * 64 + co];
        float2 v2 = *(const float2*)&h[(size_t)r0c * 64 + co + 8];
        float2 v3 = *(const float2*)&h[(size_t)r1c * 64 + co + 8];

        uint32_t ah0 = f2_to_bf2(v0), ah1 = f2_to_bf2(v1);
        uint32_t ah2 = f2_to_bf2(v2), ah3 = f2_to_bf2(v3);
        float2 h0 = bf2_to_f2(ah0), h1 = bf2_to_f2(ah1);
        float2 h2 = bf2_to_f2(ah2), h3 = bf2_to_f2(ah3);
        uint32_t al0 = f2_to_bf2(make_float2(v0.x - h0.x, v0.y - h0.y));
        uint32_t al1 = f2_to_bf2(make_float2(v1.x - h1.x, v1.y - h1.y));
        uint32_t al2 = f2_to_bf2(make_float2(v2.x - h2.x, v2.y - h2.y));
        uint32_t al3 = f2_to_bf2(make_float2(v3.x - h3.x, v3.y - h3.y));

#pragma unroll
        for (int nt = 0; nt < 12; nt++) {
            int ng = colh * 12 + nt;
            uint2 bh = sBh[ch][ng][lane];
            uint2 bl = sBl[ch][ng][lane];
            MMA_BF16(acc[nt], ah0, ah1, ah2, ah3, bh.x, bh.y);
            MMA_BF16(acc[nt], al0, al1, al2, al3, bh.x, bh.y);
            MMA_BF16(acc[nt], ah0, ah1, ah2, ah3, bl.x, bl.y);
        }
    }

    const float* bcl = bc + l * 192;
#pragma unroll
    for (int nt = 0; nt < 12; nt++) {
        int col = colh * 96 + nt * 8 + tig * 2;
        float2 b = __ldg((const float2*)&bcl[col]);
        __nv_bfloat162 o0 = __float22bfloat162_rn(
            make_float2(acc[nt][0] + b.x, acc[nt][1] + b.y));
        __nv_bfloat162 o1 = __float22bfloat162_rn(
            make_float2(acc[nt][2] + b.x, acc[nt][3] + b.y));
        if (col < 64) {
            if (r0 < n) *(__nv_bfloat162*)&qo[(size_t)r0 * 64 + col] = o0;
            if (r1 < n) *(__nv_bfloat162*)&qo[(size_t)r1 * 64 + col] = o1;
        } else {
            if (r0 < n) *(__nv_bfloat162*)&kmo[(size_t)r0 * 128 + col - 64] = o0;
            if (r1 < n) *(__nv_bfloat162*)&kmo[(size_t)r1 * 128 + col - 64] = o1;
        }
    }
}

// =====================================================================
// CSR construction
// =====================================================================
__global__ void zero_kernel(int* a, int* b, int n) {
    int i = blockIdx.x * blockDim.x + threadIdx.x;
    if (i < n) { a[i] = 0; b[i] = 0; }
}

__global__ void hist_kernel(const int* __restrict__ ei, int* __restrict__ cnt, int ne) {
    int e = blockIdx.x * blockDim.x + threadIdx.x;
    if (e < ne) atomicAdd(&cnt[ei[ne + e]], 1);
}

__global__ __launch_bounds__(1024) void scan1_kernel(
    const int* __restrict__ in, int* __restrict__ out, int* __restrict__ part, int n)
{
    __shared__ int wsum[32];
    int t = threadIdx.x;
    int i = blockIdx.x * 1024 + t;
    int v = (i < n) ? in[i] : 0;
    int x = v;
#pragma unroll
    for (int d = 1; d < 32; d <<= 1) {
        int y = __shfl_up_sync(0xffffffffu, x, d);
        if ((t & 31) >= d) x += y;
    }
    if ((t & 31) == 31) wsum[t >> 5] = x;
    __syncthreads();
    if (t < 32) {
        int s = wsum[t];
        int sx = s;
#pragma unroll
        for (int d = 1; d < 32; d <<= 1) {
            int y = __shfl_up_sync(0xffffffffu, sx, d);
            if (t >= d) sx += y;
        }
        wsum[t] = sx - s;
    }
    __syncthreads();
    int excl = x - v + wsum[t >> 5];
    if (i < n) out[i] = excl;
    if (t == 1023 && part) part[blockIdx.x] = x + wsum[31];
}

__global__ void scan3_kernel(int* __restrict__ off, const int* __restrict__ partScan, int n) {
    int i = blockIdx.x * 1024 + threadIdx.x;
    if (i < n) off[i] += partScan[blockIdx.x];
}

__global__ void scatter_kernel(const int* __restrict__ ei,
                               const int* __restrict__ off, int* __restrict__ cnt2,
                               int* __restrict__ csr, int ne)
{
    int e = blockIdx.x * blockDim.x + threadIdx.x;
    if (e < ne) {
        int s = ei[e];
        int d = ei[ne + e];
        int pos = off[d] + atomicAdd(&cnt2[d], 1);
        csr[pos] = s;
    }
}

// =====================================================================
// layer: fused edge aggregation + epilogue (warp per dst, 2 edges/warp)
// q is bf16; p_rel/4 folded into kT'.
// =====================================================================
__global__ __launch_bounds__(256) void layer_kernel(
    const float* __restrict__ hin, const __nv_bfloat16* __restrict__ qb16,
    const __nv_bfloat16* __restrict__ km,
    const int* __restrict__ off, const int* __restrict__ cnt,
    const int* __restrict__ csr,
    const float* __restrict__ Wo, const float* __restrict__ bo,
    const float* __restrict__ skp,
    float* __restrict__ hout, int n)
{
    __shared__ float sWo[64 * 64];
    {
        int t4 = threadIdx.x * 4;
#pragma unroll
        for (int i = 0; i < 4; i++) {
            int idx = t4 + i * 1024;
            *(float4*)&sWo[idx] = *(const float4*)&Wo[idx];
        }
    }
    __syncthreads();

    const int w    = threadIdx.x >> 5;
    const int lane = threadIdx.x & 31;
    const int node = blockIdx.x * 8 + w;
    if (node >= n) return;

    const int sub = lane >> 4;
    const int sl  = lane & 15;
    const int c0  = sl * 4;

    uint2 qu = *(const uint2*)&qb16[(size_t)node * 64 + c0];
    float2 q01 = bf2_to_f2(qu.x), q23 = bf2_to_f2(qu.y);
    const float4 qv = make_float4(q01.x, q01.y, q23.x, q23.y);

    const int base = off[node];
    const int deg  = cnt[node];

    float4 acc = make_float4(0.f, 0.f, 0.f, 0.f);
    float wsum = 0.f;

    for (int i0 = 0; i0 < deg; i0 += 32) {
        int idx  = i0 + lane;
        int sreg = (idx < deg) ? csr[base + idx] : 0;
        int m = deg - i0; if (m > 32) m = 32;
#pragma unroll 4
        for (int jj = 0; jj < m; jj += 2) {
            int e  = jj + sub;
            bool ok = (e < m);
            int s = __shfl_sync(0xffffffffu, sreg, e);
            if (!ok) s = 0;
            const __nv_bfloat16* row = km + (size_t)s * 128;
            uint2 ku = *(const uint2*)(row + c0);
            uint2 mu = *(const uint2*)(row + 64 + c0);
            float2 k01 = bf2_to_f2(ku.x);
            float2 k23 = bf2_to_f2(ku.y);
            float2 m01 = bf2_to_f2(mu.x);
            float2 m23 = bf2_to_f2(mu.y);
            float p = k01.x * qv.x + k01.y * qv.y + k23.x * qv.z + k23.y * qv.w;
            p += __shfl_xor_sync(0xffffffffu, p, 1);
            p += __shfl_xor_sync(0xffffffffu, p, 2);
            float wgt = ok ? __expf(p) : 0.f;
            acc.x = fmaf(wgt, m01.x, acc.x);
            acc.y = fmaf(wgt, m01.y, acc.y);
            acc.z = fmaf(wgt, m23.x, acc.z);
            acc.w = fmaf(wgt, m23.y, acc.w);
            wsum += wgt;
        }
    }

    acc.x += __shfl_xor_sync(0xffffffffu, acc.x, 16);
    acc.y += __shfl_xor_sync(0xffffffffu, acc.y, 16);
    acc.z += __shfl_xor_sync(0xffffffffu, acc.z, 16);
    acc.w += __shfl_xor_sync(0xffffffffu, acc.w, 16);
    wsum  += __shfl_xor_sync(0xffffffffu, wsum, 16);

    const float inv = 1.0f / (wsum + 1e-16f);
    float4 g;
    g.x = gelu_tanh(acc.x * inv);
    g.y = gelu_tanh(acc.y * inv);
    g.z = gelu_tanh(acc.z * inv);
    g.w = gelu_tanh(acc.w * inv);

    const int co2 = lane * 2;
    ull a = 0ull;
#pragma unroll
    for (int j4 = 0; j4 < 64; j4 += 4) {
        int jl = j4 >> 2;
        float g0 = __shfl_sync(0xffffffffu, g.x, jl);
        float g1 = __shfl_sync(0xffffffffu, g.y, jl);
        float g2 = __shfl_sync(0xffffffffu, g.z, jl);
        float g3 = __shfl_sync(0xffffffffu, g.w, jl);
        a = fma2(pack2(g0, g0), *(const ull*)&sWo[(j4    ) * 64 + co2], a);
        a = fma2(pack2(g1, g1), *(const ull*)&sWo[(j4 + 1) * 64 + co2], a);
        a = fma2(pack2(g2, g2), *(const ull*)&sWo[(j4 + 2) * 64 + co2], a);
        a = fma2(pack2(g3, g3), *(const ull*)&sWo[(j4 + 3) * 64 + co2], a);
    }

    const float sg = 1.0f / (1.0f + __expf(-skp[0]));
    float2 o = unpack2(a);
    o.x += bo[co2];
    o.y += bo[co2 + 1];
    float2 hp = *(const float2*)&hin[(size_t)node * 64 + co2];
    float r0 = fmaxf(sg * o.x + (1.0f - sg) * hp.x, 0.f);
    float r1 = fmaxf(sg * o.y + (1.0f - sg) * hp.y, 0.f);
    *(float2*)&hout[(size_t)node * 64 + co2] = make_float2(r0, r1);
}

// =====================================================================
// classifier
// =====================================================================
__global__ __launch_bounds__(256) void cls_kernel(
    const float* __restrict__ h,
    const float* __restrict__ Wc1, const float* __restrict__ bc1,
    const float* __restrict__ Wc2, const float* __restrict__ bc2,
    float* __restrict__ out, int n)
{
    const int w     = threadIdx.x >> 5;
    const int lane  = threadIdx.x & 31;
    const int node0 = (blockIdx.x * 8 + w) * 4;
    if (node0 >= n) return;
    const int c0 = lane * 2;

    float2 hv[4];
#pragma unroll
    for (int i = 0; i < 4; i++) {
        int nd = node0 + i;
        hv[i] = (nd < n) ? *(const float2*)&h[(size_t)nd * 64 + c0]
                         : make_float2(0.f, 0.f);
    }

    float acc[4] = {0.f, 0.f, 0.f, 0.f};
#pragma unroll 8
    for (int j = 0; j < 64; j += 2) {
        float w0 = Wc1[(j    ) * 32 + lane];
        float w1 = Wc1[(j + 1) * 32 + lane];
#pragma unroll
        for (int i = 0; i < 4; i++) {
            float h0 = __shfl_sync(0xffffffffu, hv[i].x, j >> 1);
            float h1 = __shfl_sync(0xffffffffu, hv[i].y, j >> 1);
            acc[i] = fmaf(h0, w0, acc[i]);
            acc[i] = fmaf(h1, w1, acc[i]);
        }
    }

    const float b1 = bc1[lane];
    float2 w2 = *(const float2*)&Wc2[lane * 2];
    const float bo0 = bc2[0], bo1 = bc2[1];
#pragma unroll
    for (int i = 0; i < 4; i++) {
        float hc = fmaxf(acc[i] + b1, 0.f);
        float o0 = hc * w2.x;
        float o1 = hc * w2.y;
#pragma unroll
        for (int m = 16; m >= 1; m >>= 1) {
            o0 += __shfl_xor_sync(0xffffffffu, o0, m);
            o1 += __shfl_xor_sync(0xffffffffu, o1, m);
        }
        int nd = node0 + i;
        if (lane == 0 && nd < n) {
            *(float2*)&out[(size_t)nd * 2] = make_float2(o0 + bo0, o1 + bo1);
        }
    }
}

// =====================================================================
extern "C" void kernel_launch(void* const* d_in, const int* in_sizes, int n_in,
                              void* d_out, int out_size)
{
    const float* x     = (const float*)d_in[0];
    const int*   ei    = (const int*)  d_in[1];
    const float* Wp    = (const float*)d_in[2];
    const float* bp    = (const float*)d_in[3];
    const float* Wk    = (const float*)d_in[4];
    const float* bk    = (const float*)d_in[5];
    const float* Wq    = (const float*)d_in[6];
    const float* bq    = (const float*)d_in[7];
    const float* Wv    = (const float*)d_in[8];
    const float* bv    = (const float*)d_in[9];
    const float* a_rel = (const float*)d_in[10];
    const float* m_rel = (const float*)d_in[11];
    const float* p_rel = (const float*)d_in[12];
    const float* Wo    = (const float*)d_in[13];
    const float* bo    = (const float*)d_in[14];
    const float* skp   = (const float*)d_in[15];
    const float* Wc1   = (const float*)d_in[16];
    const float* bc1   = (const float*)d_in[17];
    const float* Wc2   = (const float*)d_in[18];
    const float* bc2   = (const float*)d_in[19];

    const int n  = in_sizes[0] / 768;
    const int ne = in_sizes[1] / 2;

    float *h0, *h1, *bcb;
    __nv_bfloat16 *kmb, *qbb;
    uint2 *bhi, *blo, *chi, *clo;
    int *cnt, *cnt2, *off, *part, *partScan, *part2, *csr;
    cudaGetSymbolAddress((void**)&h0,  g_h0);
    cudaGetSymbolAddress((void**)&h1,  g_h1);
    cudaGetSymbolAddress((void**)&qbb, g_qb);
    cudaGetSymbolAddress((void**)&kmb, g_km);
    cudaGetSymbolAddress((void**)&bhi, g_Bhi);
    cudaGetSymbolAddress((void**)&blo, g_Blo);
    cudaGetSymbolAddress((void**)&chi, g_Chi);
    cudaGetSymbolAddress((void**)&clo, g_Clo);
    cudaGetSymbolAddress((void**)&bcb, g_bc);
    cudaGetSymbolAddress((void**)&cnt, g_cnt);
    cudaGetSymbolAddress((void**)&cnt2, g_cnt2);
    cudaGetSymbolAddress((void**)&off, g_off);
    cudaGetSymbolAddress((void**)&part, g_part);
    cudaGetSymbolAddress((void**)&partScan, g_partScan);
    cudaGetSymbolAddress((void**)&part2, g_part2);
    cudaGetSymbolAddress((void**)&csr, g_csr);

    const int gProj = (n + 127) / 128;
    const int gQkv  = (n + 127) / 128;
    const int gNode = (n + 31) / 32;
    const int gWarp = (n + 7) / 8;
    const int gE    = (ne + 255) / 256;
    const int nScanBlocks = (n + 1023) / 1024;

    // Launch order: qkv_mma at slot #4 (ncu profiles launch #4).
    wprep_kernel<<<48, 256>>>(Wp, bhi, blo);                                  // 1
    wcombpack_kernel<<<26, 256>>>(Wk, bk, Wq, bq, Wv, bv,                     // 2
                                  a_rel, m_rel, p_rel, chi, clo, bcb);
    proj_mma_kernel<<<gProj, 256>>>(x, bp, bhi, blo, h0, n);                  // 3
    qkv_mma_kernel<<<gQkv, 512>>>(h0, chi, clo, bcb, qbb, kmb, n, 0);         // 4
    zero_kernel<<<(n + 255) / 256, 256>>>(cnt, cnt2, n);                      // 5
    hist_kernel<<<gE, 256>>>(ei, cnt, ne);                                     // 6
    scan1_kernel<<<nScanBlocks, 1024>>>(cnt, off, part, n);                    // 7
    scan1_kernel<<<1, 1024>>>(part, partScan, part2, nScanBlocks);             // 8
    scan3_kernel<<<nScanBlocks, 1024>>>(off, partScan, n);                     // 9
    scatter_kernel<<<gE, 256>>>(ei, off, cnt2, csr, ne);                       // 10

    layer_kernel<<<gWarp, 256>>>(h0, qbb, kmb, off, cnt, csr,                  // 11
                                 Wo, bo, skp, h1, n);
    qkv_mma_kernel<<<gQkv, 512>>>(h1, chi, clo, bcb, qbb, kmb, n, 1);          // 12
    layer_kernel<<<gWarp, 256>>>(h1, qbb, kmb, off, cnt, csr,                  // 13
                                 Wo + 4096, bo + 64, skp + 1, h0, n);

    cls_kernel<<<gNode, 256>>>(h0, Wc1, bc1, Wc2, bc2, (float*)d_out, n);      // 14
}